// round 7
// baseline (speedup 1.0000x reference)
#include <cuda_runtime.h>
#include <cuda_bf16.h>
#include <math.h>

#define BATCH 16
#define SEQL  1024
#define DM    256
#define DI    512
#define DS    16
#define DR    16
#define NL    4
#define NC    32        // scan chunks
#define CL    (SEQL/NC) // 32 steps per chunk

typedef unsigned long long ull;

// ---------------- scratch (static device globals; no allocation) ----------------
__device__ float g_seq  [BATCH*SEQL*DM];
__device__ __nv_bfloat16 g_xnb [BATCH*SEQL*DM];
__device__ float g_xr   [BATCH*SEQL*2*DI];
__device__ float g_u    [BATCH*SEQL*DI];
__device__ __nv_bfloat16 g_ub  [BATCH*SEQL*DI];
__device__ float g_dbc  [BATCH*SEQL*64];
__device__ __nv_bfloat16 g_yb  [BATCH*SEQL*DI];
__device__ __nv_bfloat16 g_inwb[NL*DM*2*DI];
__device__ __nv_bfloat16 g_owb [NL*DI*DM];
__device__ __nv_bfloat16 g_xpwb[NL*DI*64];
__device__ float g_part [BATCH*16*DM];
__device__ float g_ca   [BATCH*NC*DI*DS];
__device__ float g_cs   [BATCH*NC*DI*DS];
__device__ float g_h0   [BATCH*NC*DI*DS];
__device__ float g_delta[BATCH*SEQL*DI];
__device__ float g_e1   [BATCH*SEQL*DI];
__device__ float g_du   [BATCH*SEQL*DI];

__device__ __forceinline__ float ex2f(float x) {
    float r; asm("ex2.approx.f32 %0, %1;" : "=f"(r) : "f"(x)); return r;
}
__device__ __forceinline__ float lg2f(float x) {
    float r; asm("lg2.approx.f32 %0, %1;" : "=f"(r) : "f"(x)); return r;
}
__device__ __forceinline__ float softplus_f(float x) {
    float t = ex2f(x * 1.44269504f);
    return (x > 15.f) ? x : 0.69314718f * lg2f(1.f + t);
}
// ---- packed f32x2 helpers (sm_100+) ----
__device__ __forceinline__ ull pk2(float lo, float hi) {
    ull r; asm("mov.b64 %0, {%1,%2};" : "=l"(r) : "f"(lo), "f"(hi)); return r;
}
__device__ __forceinline__ void upk2(ull v, float& lo, float& hi) {
    asm("mov.b64 {%0,%1}, %2;" : "=f"(lo), "=f"(hi) : "l"(v));
}
__device__ __forceinline__ ull mul2(ull a, ull b) {
    ull r; asm("mul.rn.f32x2 %0, %1, %2;" : "=l"(r) : "l"(a), "l"(b)); return r;
}
__device__ __forceinline__ ull fma2(ull a, ull b, ull c) {
    ull r; asm("fma.rn.f32x2 %0, %1, %2, %3;" : "=l"(r) : "l"(a), "l"(b), "l"(c)); return r;
}

// ---------------- fp32 -> bf16 bulk convert ----------------
__global__ void f2b_kernel(const float* __restrict__ src, __nv_bfloat16* __restrict__ dst, int n)
{
    int i = (blockIdx.x * 256 + threadIdx.x) * 4;
    if (i < n) {
        float4 v = *(const float4*)(src + i);
        __nv_bfloat162 p0 = __floats2bfloat162_rn(v.x, v.y);
        __nv_bfloat162 p1 = __floats2bfloat162_rn(v.z, v.w);
        *(uint2*)(dst + i) = make_uint2(*(unsigned*)&p0, *(unsigned*)&p1);
    }
}

// ---------------- pad x_proj_w (L,512,48) -> (L,512,64) bf16 zero-padded ----------------
__global__ void pad_xpw_kernel(const float* __restrict__ xpw, __nv_bfloat16* __restrict__ out)
{
    int idx = blockIdx.x * 256 + threadIdx.x;
    int j  = idx & 63;
    int rk = idx >> 6;
    out[idx] = __float2bfloat16((j < 48) ? xpw[rk*48 + j] : 0.f);
}

// ---------------- patch extract + LN(48) + embed + LN(256); 2 tokens per warp ----------------
__global__ void patch_embed_kernel(const float* __restrict__ x,
                                   const float* __restrict__ plg, const float* __restrict__ plb,
                                   const float* __restrict__ ew,  const float* __restrict__ eb,
                                   const float* __restrict__ elg, const float* __restrict__ elb,
                                   float* __restrict__ seq)
{
    __shared__ float sp[8][2][48];
    int warp = threadIdx.x >> 5, lane = threadIdx.x & 31;
    int tb = blockIdx.x * 16 + warp*2;

    #pragma unroll
    for (int tk = 0; tk < 2; tk++) {
        int t = tb + tk;
        int b = t >> 10, pos = t & 1023;
        int hy = pos >> 5, wx = pos & 31;
        float p1, p2 = 0.f;
        {
            int j = lane;
            int c = j >> 4, py = (j >> 2) & 3, px = j & 3;
            p1 = x[((b*3 + c)*128 + hy*4 + py)*128 + wx*4 + px];
            if (lane < 16) {
                j = 32 + lane;
                c = j >> 4; py = (j >> 2) & 3; px = j & 3;
                p2 = x[((b*3 + c)*128 + hy*4 + py)*128 + wx*4 + px];
            }
        }
        float s = p1 + p2, ss = p1*p1 + p2*p2;
        #pragma unroll
        for (int o = 16; o > 0; o >>= 1) {
            s  += __shfl_xor_sync(0xffffffffu, s,  o);
            ss += __shfl_xor_sync(0xffffffffu, ss, o);
        }
        float mu  = s * (1.f/48.f);
        float var = ss * (1.f/48.f) - mu*mu;
        float rs  = rsqrtf(var + 1e-5f);
        sp[warp][tk][lane] = (p1 - mu)*rs*plg[lane] + plb[lane];
        if (lane < 16) sp[warp][tk][32+lane] = (p2 - mu)*rs*plg[32+lane] + plb[32+lane];
    }
    __syncwarp();

    float acc0[8], acc1[8];
    #pragma unroll
    for (int i = 0; i < 8; i++) { float e = eb[lane + 32*i]; acc0[i] = e; acc1[i] = e; }
    #pragma unroll 4
    for (int j = 0; j < 48; j++) {
        float v0 = sp[warp][0][j], v1 = sp[warp][1][j];
        const float* w = ew + j*DM + lane;
        #pragma unroll
        for (int i = 0; i < 8; i++) {
            float wv = w[32*i];
            acc0[i] += v0 * wv;
            acc1[i] += v1 * wv;
        }
    }
    #pragma unroll
    for (int tk = 0; tk < 2; tk++) {
        float* acc = tk ? acc1 : acc0;
        float s2 = 0.f, ss2 = 0.f;
        #pragma unroll
        for (int i = 0; i < 8; i++) { s2 += acc[i]; ss2 += acc[i]*acc[i]; }
        #pragma unroll
        for (int o = 16; o > 0; o >>= 1) {
            s2  += __shfl_xor_sync(0xffffffffu, s2,  o);
            ss2 += __shfl_xor_sync(0xffffffffu, ss2, o);
        }
        float mu2  = s2 * (1.f/256.f);
        float var2 = ss2 * (1.f/256.f) - mu2*mu2;
        float rs2  = rsqrtf(var2 + 1e-5f);
        int t = tb + tk;
        #pragma unroll
        for (int i = 0; i < 8; i++) {
            int e = lane + 32*i;
            seq[(size_t)t*DM + e] = (acc[i] - mu2)*rs2*elg[e] + elb[e];
        }
    }
}

// ---------------- rmsnorm over DM=256, bf16 output ----------------
__global__ void rmsnorm_kernel(const float* __restrict__ in, const float* __restrict__ w,
                               __nv_bfloat16* __restrict__ out)
{
    int warp = threadIdx.x >> 5, lane = threadIdx.x & 31;
    int t = blockIdx.x * 8 + warp;
    const float4* ip = (const float4*)(in + (size_t)t*DM);
    float4 v0 = ip[lane], v1 = ip[lane+32];
    float ss = v0.x*v0.x+v0.y*v0.y+v0.z*v0.z+v0.w*v0.w
             + v1.x*v1.x+v1.y*v1.y+v1.z*v1.z+v1.w*v1.w;
    #pragma unroll
    for (int o = 16; o > 0; o >>= 1) ss += __shfl_xor_sync(0xffffffffu, ss, o);
    float sc = rsqrtf(ss*(1.f/256.f) + 1e-5f);
    const float4* wp = (const float4*)w;
    float4 w0 = wp[lane], w1 = wp[lane+32];
    __nv_bfloat162 a0 = __floats2bfloat162_rn(v0.x*sc*w0.x, v0.y*sc*w0.y);
    __nv_bfloat162 a1 = __floats2bfloat162_rn(v0.z*sc*w0.z, v0.w*sc*w0.w);
    __nv_bfloat162 b0 = __floats2bfloat162_rn(v1.x*sc*w1.x, v1.y*sc*w1.y);
    __nv_bfloat162 b1 = __floats2bfloat162_rn(v1.z*sc*w1.z, v1.w*sc*w1.w);
    __nv_bfloat16* op = out + (size_t)t*DM;
    *(uint2*)(op + lane*4)      = make_uint2(*(unsigned*)&a0, *(unsigned*)&a1);
    *(uint2*)(op + (lane+32)*4) = make_uint2(*(unsigned*)&b0, *(unsigned*)&b1);
}

// ---------------- BF16 tensor-core GEMM with ldmatrix ----------------
#define ASTR 40
#define BSTR 72

__device__ __forceinline__ void ldsm4(unsigned* r, unsigned addr) {
    asm volatile("ldmatrix.sync.aligned.m8n8.x4.shared.b16 {%0,%1,%2,%3}, [%4];"
        : "=r"(r[0]), "=r"(r[1]), "=r"(r[2]), "=r"(r[3]) : "r"(addr));
}
__device__ __forceinline__ void ldsm4t(unsigned* r, unsigned addr) {
    asm volatile("ldmatrix.sync.aligned.m8n8.x4.trans.shared.b16 {%0,%1,%2,%3}, [%4];"
        : "=r"(r[0]), "=r"(r[1]), "=r"(r[2]), "=r"(r[3]) : "r"(addr));
}

template<bool RESID>
__global__ void __launch_bounds__(256)
gemm_bf16(const __nv_bfloat16* __restrict__ A, const __nv_bfloat16* __restrict__ Bm,
          float* __restrict__ C, int M, int N, int K)
{
    __shared__ __align__(16) __nv_bfloat16 As[128*ASTR];
    __shared__ __align__(16) __nv_bfloat16 Bs[32*BSTR];
    const int tid  = threadIdx.x;
    const int m0   = blockIdx.y * 128;
    const int n0   = blockIdx.x * 64;
    const int warp = tid >> 5, lane = tid & 31;
    const int g = lane >> 2, t = lane & 3;
    const int wm = (warp & 3) * 32;
    const int wn = (warp >> 2) * 32;

    const int rowa = tid >> 2, ca = tid & 3;
    const int rowb = tid >> 3, cb = tid & 7;
    const __nv_bfloat16* Ap = A + (size_t)(m0 + rowa)*K + ca*8;
    const __nv_bfloat16* Bp = Bm + (size_t)rowb*N + n0 + cb*8;

    unsigned aBase = (unsigned)__cvta_generic_to_shared(As);
    unsigned bBase = (unsigned)__cvta_generic_to_shared(Bs);
    unsigned aAddr[2], bAddr[2];
    {
        int arow = (lane & 15);
        int akh  = (lane >> 4) * 8;
        #pragma unroll
        for (int mt = 0; mt < 2; mt++)
            aAddr[mt] = aBase + (unsigned)((wm + mt*16 + arow)*ASTR + akh)*2u;
        int bkr = ((lane >> 3) & 1)*8 + (lane & 7);
        int bnb = (lane >> 4)*8;
        #pragma unroll
        for (int bp = 0; bp < 2; bp++)
            bAddr[bp] = bBase + (unsigned)(bkr*BSTR + wn + bp*16 + bnb)*2u;
    }

    float acc[2][4][4];
    #pragma unroll
    for (int a = 0; a < 2; a++)
        #pragma unroll
        for (int b = 0; b < 4; b++)
            #pragma unroll
            for (int c = 0; c < 4; c++) acc[a][b][c] = 0.f;

    uint4 ra[2], rb;
    ra[0] = *(const uint4*)Ap;
    ra[1] = *(const uint4*)(Ap + (size_t)64*K);
    rb    = *(const uint4*)Bp;

    for (int k0 = 0; k0 < K; k0 += 32) {
        *(uint4*)&As[rowa*ASTR + ca*8]        = ra[0];
        *(uint4*)&As[(rowa + 64)*ASTR + ca*8] = ra[1];
        *(uint4*)&Bs[rowb*BSTR + cb*8]        = rb;
        __syncthreads();

        if (k0 + 32 < K) {
            ra[0] = *(const uint4*)(Ap + k0 + 32);
            ra[1] = *(const uint4*)(Ap + (size_t)64*K + k0 + 32);
            rb    = *(const uint4*)(Bp + (size_t)(k0 + 32)*N);
        }

        #pragma unroll
        for (int ks = 0; ks < 2; ks++) {
            unsigned af[2][4], bq[2][4];
            ldsm4 (af[0], aAddr[0] + ks*32u);
            ldsm4 (af[1], aAddr[1] + ks*32u);
            ldsm4t(bq[0], bAddr[0] + ks*16u*BSTR*2u);
            ldsm4t(bq[1], bAddr[1] + ks*16u*BSTR*2u);
            #pragma unroll
            for (int mt = 0; mt < 2; mt++)
                #pragma unroll
                for (int nt = 0; nt < 4; nt++) {
                    unsigned b0 = bq[nt>>1][(nt&1)*2];
                    unsigned b1 = bq[nt>>1][(nt&1)*2+1];
                    asm volatile(
                        "mma.sync.aligned.m16n8k16.row.col.f32.bf16.bf16.f32 "
                        "{%0,%1,%2,%3},{%4,%5,%6,%7},{%8,%9},{%0,%1,%2,%3};"
                        : "+f"(acc[mt][nt][0]), "+f"(acc[mt][nt][1]),
                          "+f"(acc[mt][nt][2]), "+f"(acc[mt][nt][3])
                        : "r"(af[mt][0]), "r"(af[mt][1]), "r"(af[mt][2]), "r"(af[mt][3]),
                          "r"(b0), "r"(b1));
                }
        }
        __syncthreads();
    }

    #pragma unroll
    for (int mt = 0; mt < 2; mt++)
        #pragma unroll
        for (int nt = 0; nt < 4; nt++) {
            int row = m0 + wm + mt*16 + g;
            int col = n0 + wn + nt*8 + 2*t;
            float* p0 = C + (size_t)row*N + col;
            float* p1 = C + (size_t)(row+8)*N + col;
            float2 v0 = make_float2(acc[mt][nt][0], acc[mt][nt][1]);
            float2 v1 = make_float2(acc[mt][nt][2], acc[mt][nt][3]);
            if (RESID) {
                float2 c0 = *(const float2*)p0, c1 = *(const float2*)p1;
                v0.x += c0.x; v0.y += c0.y; v1.x += c1.x; v1.y += c1.y;
            }
            *(float2*)p0 = v0;
            *(float2*)p1 = v1;
        }
}

// ---------------- depthwise causal conv(4) + SiLU (fp32 + bf16 outputs) ----------------
__global__ void conv_silu_kernel(const float* __restrict__ xr, const float* __restrict__ cw,
                                 const float* __restrict__ cb, float* __restrict__ u,
                                 __nv_bfloat16* __restrict__ ub)
{
    int d  = blockIdx.x * 256 + threadIdx.x;
    int l0 = blockIdx.y * 64;
    int b  = blockIdx.z;
    float4 w   = *(const float4*)(cw + d*4);
    float bias = cb[d];
    const float* xs = xr + ((size_t)b*SEQL)*(2*DI) + d;
    float h0 = (l0 >= 3) ? xs[(size_t)(l0-3)*(2*DI)] : 0.f;
    float h1 = (l0 >= 2) ? xs[(size_t)(l0-2)*(2*DI)] : 0.f;
    float h2 = (l0 >= 1) ? xs[(size_t)(l0-1)*(2*DI)] : 0.f;
    float* up = u + ((size_t)b*SEQL + l0)*DI + d;
    __nv_bfloat16* ubp = ub + ((size_t)b*SEQL + l0)*DI + d;
    #pragma unroll 4
    for (int i = 0; i < 64; i++) {
        float cur = xs[(size_t)(l0+i)*(2*DI)];
        float z = bias + w.x*h0 + w.y*h1 + w.z*h2 + w.w*cur;
        float sv = z / (1.f + __expf(-z));
        up[(size_t)i*DI]  = sv;
        ubp[(size_t)i*DI] = __float2bfloat16(sv);
        h0 = h1; h1 = h2; h2 = cur;
    }
}

// ---------------- dt precompute: delta, e1=exp2(delta*a0), du=delta*u ----------------
__global__ void __launch_bounds__(128)
dt_kernel(const float* __restrict__ dbc, const float* __restrict__ dtw,
          const float* __restrict__ dtb, const float* __restrict__ Alog,
          const float* __restrict__ u,
          float* __restrict__ delta, float* __restrict__ e1a, float* __restrict__ du)
{
    __shared__ float sd[DR];
    int t   = blockIdx.x;
    int tid = threadIdx.x;
    if (tid < DR) sd[tid] = dbc[(size_t)t*64 + tid];
    __syncthreads();
    #pragma unroll
    for (int jj = 0; jj < 4; jj++) {
        int d = tid + jj*128;
        float acc = dtb[d];
        #pragma unroll
        for (int r = 0; r < DR; r++) acc += sd[r] * dtw[r*DI + d];
        float dl  = softplus_f(acc);
        float a20 = -__expf(Alog[d*DS]) * 1.44269504f;
        size_t idx = (size_t)t*DI + d;
        delta[idx] = dl;
        e1a[idx]   = ex2f(dl * a20);
        du[idx]    = dl * u[idx];
    }
}

// ---------------- chunked scan pass 1: local cumA + local state ----------------
__global__ void __launch_bounds__(128)
scan_pass1(const float* __restrict__ e1a, const float* __restrict__ du,
           const float* __restrict__ delta,
           const float* __restrict__ dbc,  const float* __restrict__ Alog,
           float* __restrict__ ca, float* __restrict__ cs)
{
    int d = blockIdx.x * 128 + threadIdx.x;
    int c = blockIdx.y;
    int b = blockIdx.z;

    float a2[DS];
    #pragma unroll
    for (int n = 0; n < DS; n++) a2[n] = -__expf(Alog[d*DS + n]) * 1.44269504f;
    bool chain = true;
    #pragma unroll
    for (int n = 1; n < DS; n++)
        if (fabsf(a2[n] - (float)(n+1)*a2[0]) > 1e-4f*fabsf(a2[n])) chain = false;

    const float* bc    = dbc   + ((size_t)b*SEQL + c*CL)*64;
    const float* e1p   = e1a   + ((size_t)b*SEQL + c*CL)*DI + d;
    const float* dup   = du    + ((size_t)b*SEQL + c*CL)*DI + d;
    const float* dlp   = delta + ((size_t)b*SEQL + c*CL)*DI + d;
    size_t o = (((size_t)b*NC + c)*DI + d)*DS;

    if (chain) {
        ull p2[8], s2[8];
        #pragma unroll
        for (int q = 0; q < 8; q++) { p2[q] = pk2(1.f, 1.f); s2[q] = 0ull; }
        for (int l = 0; l < CL; l++) {
            float e1  = e1p[(size_t)l*DI];
            float duv = dup[(size_t)l*DI];
            float e1s = e1*e1;
            ull ep   = pk2(e1, e1s);
            ull es2  = pk2(e1s, e1s);
            ull duv2 = pk2(duv, duv);
            const ulonglong2* B4 = (const ulonglong2*)(bc + (size_t)l*64 + 16);
            #pragma unroll
            for (int j = 0; j < 4; j++) {
                ulonglong2 Bp = B4[j];
                ull db0 = mul2(Bp.x, duv2);
                s2[2*j]   = fma2(ep, s2[2*j],   db0);
                p2[2*j]   = mul2(p2[2*j], ep);
                ep = mul2(ep, es2);
                ull db1 = mul2(Bp.y, duv2);
                s2[2*j+1] = fma2(ep, s2[2*j+1], db1);
                p2[2*j+1] = mul2(p2[2*j+1], ep);
                if (j < 3) ep = mul2(ep, es2);
            }
        }
        #pragma unroll
        for (int q = 0; q < 8; q++) {
            ((ull*)(ca + o))[q] = p2[q];
            ((ull*)(cs + o))[q] = s2[q];
        }
    } else {
        float p[DS], s[DS];
        #pragma unroll
        for (int n = 0; n < DS; n++) { p[n] = 1.f; s[n] = 0.f; }
        for (int l = 0; l < CL; l++) {
            float dl  = dlp[(size_t)l*DI];
            float duv = dup[(size_t)l*DI];
            const float4* Bv = (const float4*)(bc + (size_t)l*64 + 16);
            #pragma unroll
            for (int q = 0; q < 4; q++) {
                float4 Bq = Bv[q];
                float e;
                e = ex2f(dl*a2[4*q+0]); p[4*q+0]*=e; s[4*q+0]=e*s[4*q+0]+duv*Bq.x;
                e = ex2f(dl*a2[4*q+1]); p[4*q+1]*=e; s[4*q+1]=e*s[4*q+1]+duv*Bq.y;
                e = ex2f(dl*a2[4*q+2]); p[4*q+2]*=e; s[4*q+2]=e*s[4*q+2]+duv*Bq.z;
                e = ex2f(dl*a2[4*q+3]); p[4*q+3]*=e; s[4*q+3]=e*s[4*q+3]+duv*Bq.w;
            }
        }
        #pragma unroll
        for (int q = 0; q < 4; q++) {
            ((float4*)(ca + o))[q] = make_float4(p[4*q], p[4*q+1], p[4*q+2], p[4*q+3]);
            ((float4*)(cs + o))[q] = make_float4(s[4*q], s[4*q+1], s[4*q+2], s[4*q+3]);
        }
    }
}

// ---------------- pass 2: combine chunk transitions -> h0 per chunk ----------------
__global__ void __launch_bounds__(DI)
scan_pass2(const float* __restrict__ ca, const float* __restrict__ cs,
           float* __restrict__ h0)
{
    int b = blockIdx.x, d = threadIdx.x;
    float h[DS];
    #pragma unroll
    for (int n = 0; n < DS; n++) h[n] = 0.f;
    for (int c = 0; c < NC; c++) {
        size_t o = (((size_t)b*NC + c)*DI + d)*DS;
        #pragma unroll
        for (int q = 0; q < 4; q++)
            ((float4*)(h0 + o))[q] = make_float4(h[4*q], h[4*q+1], h[4*q+2], h[4*q+3]);
        #pragma unroll
        for (int q = 0; q < 4; q++) {
            float4 pq = ((const float4*)(ca + o))[q];
            float4 sq = ((const float4*)(cs + o))[q];
            h[4*q+0] = pq.x*h[4*q+0] + sq.x;
            h[4*q+1] = pq.y*h[4*q+1] + sq.y;
            h[4*q+2] = pq.z*h[4*q+2] + sq.z;
            h[4*q+3] = pq.w*h[4*q+3] + sq.w;
        }
    }
}

// ---------------- pass 3: re-scan from h0, emit y(bf16) = (scan + u*D) * silu(res) ----------------
__global__ void __launch_bounds__(128)
scan_pass3(const float* __restrict__ e1a, const float* __restrict__ du,
           const float* __restrict__ delta,
           const float* __restrict__ u,   const float* __restrict__ xr,
           const float* __restrict__ dbc, const float* __restrict__ Alog,
           const float* __restrict__ Dp,  const float* __restrict__ h0,
           __nv_bfloat16* __restrict__ y)
{
    int d = blockIdx.x * 128 + threadIdx.x;
    int c = blockIdx.y;
    int b = blockIdx.z;

    float a2[DS];
    #pragma unroll
    for (int n = 0; n < DS; n++) a2[n] = -__expf(Alog[d*DS + n]) * 1.44269504f;
    bool chain = true;
    #pragma unroll
    for (int n = 1; n < DS; n++)
        if (fabsf(a2[n] - (float)(n+1)*a2[0]) > 1e-4f*fabsf(a2[n])) chain = false;

    float Dv = Dp[d];

    const float* bc    = dbc   + ((size_t)b*SEQL + c*CL)*64;
    const float* e1p   = e1a   + ((size_t)b*SEQL + c*CL)*DI + d;
    const float* dup   = du    + ((size_t)b*SEQL + c*CL)*DI + d;
    const float* dlp   = delta + ((size_t)b*SEQL + c*CL)*DI + d;
    const float* uptr  = u     + ((size_t)b*SEQL + c*CL)*DI + d;
    const float* rptr  = xr    + ((size_t)b*SEQL + c*CL)*2*DI + DI + d;
    __nv_bfloat16* yptr = y    + ((size_t)b*SEQL + c*CL)*DI + d;
    size_t o0 = (((size_t)b*NC + c)*DI + d)*DS;

    if (chain) {
        ull h2[8];
        #pragma unroll
        for (int q = 0; q < 8; q++) h2[q] = ((const ull*)(h0 + o0))[q];
        for (int l = 0; l < CL; l++) {
            float e1  = e1p[(size_t)l*DI];
            float duv = dup[(size_t)l*DI];
            float uv  = uptr[(size_t)l*DI];
            float res = rptr[(size_t)l*2*DI];
            float e1s = e1*e1;
            ull ep   = pk2(e1, e1s);
            ull es2  = pk2(e1s, e1s);
            ull duv2 = pk2(duv, duv);
            const ulonglong2* B4 = (const ulonglong2*)(bc + (size_t)l*64 + 16);
            const ulonglong2* C4 = (const ulonglong2*)(bc + (size_t)l*64 + 32);
            ull y2 = 0ull;
            #pragma unroll
            for (int j = 0; j < 4; j++) {
                ulonglong2 Bp = B4[j], Cp = C4[j];
                ull db0 = mul2(Bp.x, duv2);
                h2[2*j] = fma2(ep, h2[2*j], db0);
                y2 = fma2(h2[2*j], Cp.x, y2);
                ep = mul2(ep, es2);
                ull db1 = mul2(Bp.y, duv2);
                h2[2*j+1] = fma2(ep, h2[2*j+1], db1);
                y2 = fma2(h2[2*j+1], Cp.y, y2);
                if (j < 3) ep = mul2(ep, es2);
            }
            float ylo, yhi; upk2(y2, ylo, yhi);
            float ov = ylo + yhi + uv*Dv;
            ov *= res / (1.f + __expf(-res));
            yptr[(size_t)l*DI] = __float2bfloat16(ov);
        }
    } else {
        float h[DS];
        #pragma unroll
        for (int q = 0; q < 4; q++) {
            float4 hq = ((const float4*)(h0 + o0))[q];
            h[4*q] = hq.x; h[4*q+1] = hq.y; h[4*q+2] = hq.z; h[4*q+3] = hq.w;
        }
        for (int l = 0; l < CL; l++) {
            float dl  = dlp[(size_t)l*DI];
            float duv = dup[(size_t)l*DI];
            float uv  = uptr[(size_t)l*DI];
            float res = rptr[(size_t)l*2*DI];
            const float4* Bv = (const float4*)(bc + (size_t)l*64 + 16);
            const float4* Cv = (const float4*)(bc + (size_t)l*64 + 32);
            float yv = 0.f;
            #pragma unroll
            for (int q = 0; q < 4; q++) {
                float4 Bq = Bv[q], Cq = Cv[q];
                float e;
                e = ex2f(dl*a2[4*q+0]); h[4*q+0]=e*h[4*q+0]+duv*Bq.x; yv += h[4*q+0]*Cq.x;
                e = ex2f(dl*a2[4*q+1]); h[4*q+1]=e*h[4*q+1]+duv*Bq.y; yv += h[4*q+1]*Cq.y;
                e = ex2f(dl*a2[4*q+2]); h[4*q+2]=e*h[4*q+2]+duv*Bq.z; yv += h[4*q+2]*Cq.z;
                e = ex2f(dl*a2[4*q+3]); h[4*q+3]=e*h[4*q+3]+duv*Bq.w; yv += h[4*q+3]*Cq.w;
            }
            float ov = yv + uv*Dv;
            ov *= res / (1.f + __expf(-res));
            yptr[(size_t)l*DI] = __float2bfloat16(ov);
        }
    }
}

// ---------------- deterministic two-stage mean over L ----------------
__global__ void mean_part_kernel(const float* __restrict__ seq, float* __restrict__ part)
{
    int b = blockIdx.x, c = blockIdx.y, e = threadIdx.x;
    const float* p = seq + ((size_t)b*SEQL + c*64)*DM + e;
    float s = 0.f;
    #pragma unroll 8
    for (int i = 0; i < 64; i++) s += p[(size_t)i*DM];
    part[(b*16 + c)*DM + e] = s;
}
__global__ void mean_final_kernel(const float* __restrict__ part, float* __restrict__ out)
{
    int b = blockIdx.x, e = threadIdx.x;
    float s = 0.f;
    #pragma unroll
    for (int c = 0; c < 16; c++) s += part[(b*16 + c)*DM + e];
    out[b*DM + e] = s * (1.f/1024.f);
}

// ---------------- launch ----------------
extern "C" void kernel_launch(void* const* d_in, const int* in_sizes, int n_in,
                              void* d_out, int out_size)
{
    const float* x    = (const float*)d_in[0];
    const float* plg  = (const float*)d_in[1];
    const float* plb  = (const float*)d_in[2];
    const float* ew   = (const float*)d_in[3];
    const float* eb   = (const float*)d_in[4];
    const float* elg  = (const float*)d_in[5];
    const float* elb  = (const float*)d_in[6];
    const float* rmsw = (const float*)d_in[7];
    const float* inw  = (const float*)d_in[8];
    const float* cw   = (const float*)d_in[9];
    const float* cb   = (const float*)d_in[10];
    const float* xpw  = (const float*)d_in[11];
    const float* dtw  = (const float*)d_in[12];
    const float* dtb  = (const float*)d_in[13];
    const float* Alog = (const float*)d_in[14];
    const float* Dpar = (const float*)d_in[15];
    const float* ow   = (const float*)d_in[16];

    float *seq, *xr, *u, *dbc, *part, *ca, *cs, *h0, *delta, *e1a, *du;
    __nv_bfloat16 *xnb, *ub, *yb, *inwb, *owb, *xpwb;
    cudaGetSymbolAddress((void**)&seq,   g_seq);
    cudaGetSymbolAddress((void**)&xnb,   g_xnb);
    cudaGetSymbolAddress((void**)&xr,    g_xr);
    cudaGetSymbolAddress((void**)&u,     g_u);
    cudaGetSymbolAddress((void**)&ub,    g_ub);
    cudaGetSymbolAddress((void**)&dbc,   g_dbc);
    cudaGetSymbolAddress((void**)&yb,    g_yb);
    cudaGetSymbolAddress((void**)&inwb,  g_inwb);
    cudaGetSymbolAddress((void**)&owb,   g_owb);
    cudaGetSymbolAddress((void**)&xpwb,  g_xpwb);
    cudaGetSymbolAddress((void**)&part,  g_part);
    cudaGetSymbolAddress((void**)&ca,    g_ca);
    cudaGetSymbolAddress((void**)&cs,    g_cs);
    cudaGetSymbolAddress((void**)&h0,    g_h0);
    cudaGetSymbolAddress((void**)&delta, g_delta);
    cudaGetSymbolAddress((void**)&e1a,   g_e1);
    cudaGetSymbolAddress((void**)&du,    g_du);

    const int M = BATCH * SEQL;  // 16384

    f2b_kernel<<<(NL*DM*2*DI/4 + 255)/256, 256>>>(inw, inwb, NL*DM*2*DI);
    f2b_kernel<<<(NL*DI*DM/4 + 255)/256, 256>>>(ow, owb, NL*DI*DM);
    pad_xpw_kernel<<<NL*DI*64/256, 256>>>(xpw, xpwb);
    patch_embed_kernel<<<1024, 256>>>(x, plg, plb, ew, eb, elg, elb, seq);

    for (int L = 0; L < NL; L++) {
        rmsnorm_kernel<<<2048, 256>>>(seq, rmsw + L*DM, xnb);

        // in_proj: (16384,256) @ (256,1024)
        gemm_bf16<false><<<dim3(16, 128), 256>>>(
            xnb, inwb + (size_t)L*DM*2*DI, xr, M, 2*DI, DM);

        conv_silu_kernel<<<dim3(2,16,16), 256>>>(xr, cw + L*DI*4, cb + L*DI, u, ub);

        // x_proj: (16384,512) @ (512,64pad)
        gemm_bf16<false><<<dim3(1, 128), 256>>>(
            ub, xpwb + (size_t)L*DI*64, dbc, M, 64, DI);

        dt_kernel<<<M, 128>>>(dbc, dtw + L*DR*DI, dtb + L*DI,
                              Alog + L*DI*DS, u, delta, e1a, du);

        scan_pass1<<<dim3(4, NC, BATCH), 128>>>(e1a, du, delta, dbc,
                                                Alog + L*DI*DS, ca, cs);
        scan_pass2<<<BATCH, DI>>>(ca, cs, h0);
        scan_pass3<<<dim3(4, NC, BATCH), 128>>>(e1a, du, delta, u, xr, dbc,
                                                Alog + L*DI*DS, Dpar + L*DI,
                                                h0, yb);

        // out_proj (+residual into seq): (16384,512) @ (512,256)
        gemm_bf16<true><<<dim3(4, 128), 256>>>(
            yb, owb + (size_t)L*DI*DM, seq, M, DM, DI);
    }

    mean_part_kernel<<<dim3(16,16), 256>>>(seq, part);
    mean_final_kernel<<<16, 256>>>(part, (float*)d_out);
}

// round 9
// speedup vs baseline: 1.1631x; 1.1631x over previous
#include <cuda_runtime.h>
#include <cuda_bf16.h>
#include <math.h>

#define BATCH 16
#define SEQL  1024
#define DM    256
#define DI    512
#define DS    16
#define DR    16
#define NL    4
#define NC    16        // scan chunks
#define CL    (SEQL/NC) // 64 steps per chunk

typedef unsigned long long ull;

// ---------------- scratch (static device globals; no allocation) ----------------
__device__ float g_seq  [BATCH*SEQL*DM];
__device__ __nv_bfloat16 g_xnb [BATCH*SEQL*DM];
__device__ float g_xs   [BATCH*SEQL*DI];        // in_proj xs-half (fp32, feeds conv)
__device__ __nv_bfloat16 g_resb[BATCH*SEQL*DI]; // in_proj res-half (bf16, feeds pass3)
__device__ __nv_bfloat16 g_ub  [BATCH*SEQL*DI]; // conv+silu output (bf16, sole copy)
__device__ float g_dbc  [BATCH*SEQL*64];
__device__ __nv_bfloat16 g_yb  [BATCH*SEQL*DI];
__device__ __nv_bfloat16 g_inwb[NL*DM*2*DI];
__device__ __nv_bfloat16 g_owb [NL*DI*DM];
__device__ __nv_bfloat16 g_xpwb[NL*DI*64];
__device__ float g_part [BATCH*16*DM];
__device__ float g_ca   [BATCH*NC*DI*DS];
__device__ float g_cs   [BATCH*NC*DI*DS];
__device__ float g_h0   [BATCH*NC*DI*DS];

__device__ __forceinline__ float ex2f(float x) {
    float r; asm("ex2.approx.f32 %0, %1;" : "=f"(r) : "f"(x)); return r;
}
__device__ __forceinline__ float lg2f(float x) {
    float r; asm("lg2.approx.f32 %0, %1;" : "=f"(r) : "f"(x)); return r;
}
__device__ __forceinline__ float softplus_f(float x) {
    float t = ex2f(x * 1.44269504f);
    return (x > 15.f) ? x : 0.69314718f * lg2f(1.f + t);
}
// ---- packed f32x2 helpers (sm_100+) ----
__device__ __forceinline__ ull pk2(float lo, float hi) {
    ull r; asm("mov.b64 %0, {%1,%2};" : "=l"(r) : "f"(lo), "f"(hi)); return r;
}
__device__ __forceinline__ void upk2(ull v, float& lo, float& hi) {
    asm("mov.b64 {%0,%1}, %2;" : "=f"(lo), "=f"(hi) : "l"(v));
}
__device__ __forceinline__ ull mul2(ull a, ull b) {
    ull r; asm("mul.rn.f32x2 %0, %1, %2;" : "=l"(r) : "l"(a), "l"(b)); return r;
}
__device__ __forceinline__ ull fma2(ull a, ull b, ull c) {
    ull r; asm("fma.rn.f32x2 %0, %1, %2, %3;" : "=l"(r) : "l"(a), "l"(b), "l"(c)); return r;
}

// ---------------- fp32 -> bf16 bulk convert ----------------
__global__ void f2b_kernel(const float* __restrict__ src, __nv_bfloat16* __restrict__ dst, int n)
{
    int i = (blockIdx.x * 256 + threadIdx.x) * 4;
    if (i < n) {
        float4 v = *(const float4*)(src + i);
        __nv_bfloat162 p0 = __floats2bfloat162_rn(v.x, v.y);
        __nv_bfloat162 p1 = __floats2bfloat162_rn(v.z, v.w);
        *(uint2*)(dst + i) = make_uint2(*(unsigned*)&p0, *(unsigned*)&p1);
    }
}

// ---------------- pad x_proj_w (L,512,48) -> (L,512,64) bf16 zero-padded ----------------
__global__ void pad_xpw_kernel(const float* __restrict__ xpw, __nv_bfloat16* __restrict__ out)
{
    int idx = blockIdx.x * 256 + threadIdx.x;
    int j  = idx & 63;
    int rk = idx >> 6;
    out[idx] = __float2bfloat16((j < 48) ? xpw[rk*48 + j] : 0.f);
}

// ---------------- patch extract + LN(48) + embed + LN(256); 2 tokens per warp ----------------
__global__ void patch_embed_kernel(const float* __restrict__ x,
                                   const float* __restrict__ plg, const float* __restrict__ plb,
                                   const float* __restrict__ ew,  const float* __restrict__ eb,
                                   const float* __restrict__ elg, const float* __restrict__ elb,
                                   float* __restrict__ seq)
{
    __shared__ float sp[8][2][48];
    int warp = threadIdx.x >> 5, lane = threadIdx.x & 31;
    int tb = blockIdx.x * 16 + warp*2;

    #pragma unroll
    for (int tk = 0; tk < 2; tk++) {
        int t = tb + tk;
        int b = t >> 10, pos = t & 1023;
        int hy = pos >> 5, wx = pos & 31;
        float p1, p2 = 0.f;
        {
            int j = lane;
            int c = j >> 4, py = (j >> 2) & 3, px = j & 3;
            p1 = x[((b*3 + c)*128 + hy*4 + py)*128 + wx*4 + px];
            if (lane < 16) {
                j = 32 + lane;
                c = j >> 4; py = (j >> 2) & 3; px = j & 3;
                p2 = x[((b*3 + c)*128 + hy*4 + py)*128 + wx*4 + px];
            }
        }
        float s = p1 + p2, ss = p1*p1 + p2*p2;
        #pragma unroll
        for (int o = 16; o > 0; o >>= 1) {
            s  += __shfl_xor_sync(0xffffffffu, s,  o);
            ss += __shfl_xor_sync(0xffffffffu, ss, o);
        }
        float mu  = s * (1.f/48.f);
        float var = ss * (1.f/48.f) - mu*mu;
        float rs  = rsqrtf(var + 1e-5f);
        sp[warp][tk][lane] = (p1 - mu)*rs*plg[lane] + plb[lane];
        if (lane < 16) sp[warp][tk][32+lane] = (p2 - mu)*rs*plg[32+lane] + plb[32+lane];
    }
    __syncwarp();

    float acc0[8], acc1[8];
    #pragma unroll
    for (int i = 0; i < 8; i++) { float e = eb[lane + 32*i]; acc0[i] = e; acc1[i] = e; }
    #pragma unroll 4
    for (int j = 0; j < 48; j++) {
        float v0 = sp[warp][0][j], v1 = sp[warp][1][j];
        const float* w = ew + j*DM + lane;
        #pragma unroll
        for (int i = 0; i < 8; i++) {
            float wv = w[32*i];
            acc0[i] += v0 * wv;
            acc1[i] += v1 * wv;
        }
    }
    #pragma unroll
    for (int tk = 0; tk < 2; tk++) {
        float* acc = tk ? acc1 : acc0;
        float s2 = 0.f, ss2 = 0.f;
        #pragma unroll
        for (int i = 0; i < 8; i++) { s2 += acc[i]; ss2 += acc[i]*acc[i]; }
        #pragma unroll
        for (int o = 16; o > 0; o >>= 1) {
            s2  += __shfl_xor_sync(0xffffffffu, s2,  o);
            ss2 += __shfl_xor_sync(0xffffffffu, ss2, o);
        }
        float mu2  = s2 * (1.f/256.f);
        float var2 = ss2 * (1.f/256.f) - mu2*mu2;
        float rs2  = rsqrtf(var2 + 1e-5f);
        int t = tb + tk;
        #pragma unroll
        for (int i = 0; i < 8; i++) {
            int e = lane + 32*i;
            seq[(size_t)t*DM + e] = (acc[i] - mu2)*rs2*elg[e] + elb[e];
        }
    }
}

// ---------------- rmsnorm over DM=256, bf16 output ----------------
__global__ void rmsnorm_kernel(const float* __restrict__ in, const float* __restrict__ w,
                               __nv_bfloat16* __restrict__ out)
{
    int warp = threadIdx.x >> 5, lane = threadIdx.x & 31;
    int t = blockIdx.x * 8 + warp;
    const float4* ip = (const float4*)(in + (size_t)t*DM);
    float4 v0 = ip[lane], v1 = ip[lane+32];
    float ss = v0.x*v0.x+v0.y*v0.y+v0.z*v0.z+v0.w*v0.w
             + v1.x*v1.x+v1.y*v1.y+v1.z*v1.z+v1.w*v1.w;
    #pragma unroll
    for (int o = 16; o > 0; o >>= 1) ss += __shfl_xor_sync(0xffffffffu, ss, o);
    float sc = rsqrtf(ss*(1.f/256.f) + 1e-5f);
    const float4* wp = (const float4*)w;
    float4 w0 = wp[lane], w1 = wp[lane+32];
    __nv_bfloat162 a0 = __floats2bfloat162_rn(v0.x*sc*w0.x, v0.y*sc*w0.y);
    __nv_bfloat162 a1 = __floats2bfloat162_rn(v0.z*sc*w0.z, v0.w*sc*w0.w);
    __nv_bfloat162 b0 = __floats2bfloat162_rn(v1.x*sc*w1.x, v1.y*sc*w1.y);
    __nv_bfloat162 b1 = __floats2bfloat162_rn(v1.z*sc*w1.z, v1.w*sc*w1.w);
    __nv_bfloat16* op = out + (size_t)t*DM;
    *(uint2*)(op + lane*4)      = make_uint2(*(unsigned*)&a0, *(unsigned*)&a1);
    *(uint2*)(op + (lane+32)*4) = make_uint2(*(unsigned*)&b0, *(unsigned*)&b1);
}

// ---------------- BF16 tensor-core GEMM with ldmatrix ----------------
// MODE 0: C fp32. MODE 1: C fp32 += (residual). MODE 2 (in_proj split):
//   cols [0,512)   -> C  fp32 [M,512] (xs half)
//   cols [512,1024)-> Rb bf16 [M,512] (res half)
#define ASTR 40
#define BSTR 72

__device__ __forceinline__ void ldsm4(unsigned* r, unsigned addr) {
    asm volatile("ldmatrix.sync.aligned.m8n8.x4.shared.b16 {%0,%1,%2,%3}, [%4];"
        : "=r"(r[0]), "=r"(r[1]), "=r"(r[2]), "=r"(r[3]) : "r"(addr));
}
__device__ __forceinline__ void ldsm4t(unsigned* r, unsigned addr) {
    asm volatile("ldmatrix.sync.aligned.m8n8.x4.trans.shared.b16 {%0,%1,%2,%3}, [%4];"
        : "=r"(r[0]), "=r"(r[1]), "=r"(r[2]), "=r"(r[3]) : "r"(addr));
}

template<int MODE>
__global__ void __launch_bounds__(256)
gemm_bf16(const __nv_bfloat16* __restrict__ A, const __nv_bfloat16* __restrict__ Bm,
          float* __restrict__ C, __nv_bfloat16* __restrict__ Rb,
          int M, int N, int K)
{
    __shared__ __align__(16) __nv_bfloat16 As[128*ASTR];
    __shared__ __align__(16) __nv_bfloat16 Bs[32*BSTR];
    const int tid  = threadIdx.x;
    const int m0   = blockIdx.y * 128;
    const int n0   = blockIdx.x * 64;
    const int warp = tid >> 5, lane = tid & 31;
    const int g = lane >> 2, t = lane & 3;
    const int wm = (warp & 3) * 32;
    const int wn = (warp >> 2) * 32;

    const int rowa = tid >> 2, ca = tid & 3;
    const int rowb = tid >> 3, cb = tid & 7;
    const __nv_bfloat16* Ap = A + (size_t)(m0 + rowa)*K + ca*8;
    const __nv_bfloat16* Bp = Bm + (size_t)rowb*N + n0 + cb*8;

    unsigned aBase = (unsigned)__cvta_generic_to_shared(As);
    unsigned bBase = (unsigned)__cvta_generic_to_shared(Bs);
    unsigned aAddr[2], bAddr[2];
    {
        int arow = (lane & 15);
        int akh  = (lane >> 4) * 8;
        #pragma unroll
        for (int mt = 0; mt < 2; mt++)
            aAddr[mt] = aBase + (unsigned)((wm + mt*16 + arow)*ASTR + akh)*2u;
        int bkr = ((lane >> 3) & 1)*8 + (lane & 7);
        int bnb = (lane >> 4)*8;
        #pragma unroll
        for (int bp = 0; bp < 2; bp++)
            bAddr[bp] = bBase + (unsigned)(bkr*BSTR + wn + bp*16 + bnb)*2u;
    }

    float acc[2][4][4];
    #pragma unroll
    for (int a = 0; a < 2; a++)
        #pragma unroll
        for (int b = 0; b < 4; b++)
            #pragma unroll
            for (int c = 0; c < 4; c++) acc[a][b][c] = 0.f;

    uint4 ra[2], rb;
    ra[0] = *(const uint4*)Ap;
    ra[1] = *(const uint4*)(Ap + (size_t)64*K);
    rb    = *(const uint4*)Bp;

    for (int k0 = 0; k0 < K; k0 += 32) {
        *(uint4*)&As[rowa*ASTR + ca*8]        = ra[0];
        *(uint4*)&As[(rowa + 64)*ASTR + ca*8] = ra[1];
        *(uint4*)&Bs[rowb*BSTR + cb*8]        = rb;
        __syncthreads();

        if (k0 + 32 < K) {
            ra[0] = *(const uint4*)(Ap + k0 + 32);
            ra[1] = *(const uint4*)(Ap + (size_t)64*K + k0 + 32);
            rb    = *(const uint4*)(Bp + (size_t)(k0 + 32)*N);
        }

        #pragma unroll
        for (int ks = 0; ks < 2; ks++) {
            unsigned af[2][4], bq[2][4];
            ldsm4 (af[0], aAddr[0] + ks*32u);
            ldsm4 (af[1], aAddr[1] + ks*32u);
            ldsm4t(bq[0], bAddr[0] + ks*16u*BSTR*2u);
            ldsm4t(bq[1], bAddr[1] + ks*16u*BSTR*2u);
            #pragma unroll
            for (int mt = 0; mt < 2; mt++)
                #pragma unroll
                for (int nt = 0; nt < 4; nt++) {
                    unsigned b0 = bq[nt>>1][(nt&1)*2];
                    unsigned b1 = bq[nt>>1][(nt&1)*2+1];
                    asm volatile(
                        "mma.sync.aligned.m16n8k16.row.col.f32.bf16.bf16.f32 "
                        "{%0,%1,%2,%3},{%4,%5,%6,%7},{%8,%9},{%0,%1,%2,%3};"
                        : "+f"(acc[mt][nt][0]), "+f"(acc[mt][nt][1]),
                          "+f"(acc[mt][nt][2]), "+f"(acc[mt][nt][3])
                        : "r"(af[mt][0]), "r"(af[mt][1]), "r"(af[mt][2]), "r"(af[mt][3]),
                          "r"(b0), "r"(b1));
                }
        }
        __syncthreads();
    }

    #pragma unroll
    for (int mt = 0; mt < 2; mt++)
        #pragma unroll
        for (int nt = 0; nt < 4; nt++) {
            int row = m0 + wm + mt*16 + g;
            int col = n0 + wn + nt*8 + 2*t;
            if (MODE == 2 && n0 >= 512) {
                int rc = col - 512;   // even -> 4B-aligned bf16x2 store
                __nv_bfloat162 v0 = __floats2bfloat162_rn(acc[mt][nt][0], acc[mt][nt][1]);
                __nv_bfloat162 v1 = __floats2bfloat162_rn(acc[mt][nt][2], acc[mt][nt][3]);
                *(unsigned*)(Rb + (size_t)row*DI + rc)     = *(unsigned*)&v0;
                *(unsigned*)(Rb + (size_t)(row+8)*DI + rc) = *(unsigned*)&v1;
            } else {
                int outN = (MODE == 2) ? DI : N;
                float* p0 = C + (size_t)row*outN + col;
                float* p1 = C + (size_t)(row+8)*outN + col;
                float2 v0 = make_float2(acc[mt][nt][0], acc[mt][nt][1]);
                float2 v1 = make_float2(acc[mt][nt][2], acc[mt][nt][3]);
                if (MODE == 1) {
                    float2 c0 = *(const float2*)p0, c1 = *(const float2*)p1;
                    v0.x += c0.x; v0.y += c0.y; v1.x += c1.x; v1.y += c1.y;
                }
                *(float2*)p0 = v0;
                *(float2*)p1 = v1;
            }
        }
}

// ---------------- depthwise causal conv(4) + SiLU -> ub (bf16 only) ----------------
__global__ void conv_silu_kernel(const float* __restrict__ xs, const float* __restrict__ cw,
                                 const float* __restrict__ cb, __nv_bfloat16* __restrict__ ub)
{
    int d  = blockIdx.x * 256 + threadIdx.x;
    int l0 = blockIdx.y * 64;
    int b  = blockIdx.z;
    float4 w   = *(const float4*)(cw + d*4);
    float bias = cb[d];
    const float* xp = xs + ((size_t)b*SEQL)*DI + d;
    float h0 = (l0 >= 3) ? xp[(size_t)(l0-3)*DI] : 0.f;
    float h1 = (l0 >= 2) ? xp[(size_t)(l0-2)*DI] : 0.f;
    float h2 = (l0 >= 1) ? xp[(size_t)(l0-1)*DI] : 0.f;
    __nv_bfloat16* ubp = ub + ((size_t)b*SEQL + l0)*DI + d;
    #pragma unroll 4
    for (int i = 0; i < 64; i++) {
        float cur = xp[(size_t)(l0+i)*DI];
        float z = bias + w.x*h0 + w.y*h1 + w.z*h2 + w.w*cur;
        float sv = z / (1.f + __expf(-z));
        ubp[(size_t)i*DI] = __float2bfloat16(sv);
        h0 = h1; h1 = h2; h2 = cur;
    }
}

// ---- dt_proj + softplus fused inline ----
__device__ __forceinline__ float dt_softplus(const float4* dtv, const float* w, float bias)
{
    float4 t0 = dtv[0], t1 = dtv[1], t2 = dtv[2], t3 = dtv[3];
    float acc = bias;
    acc += t0.x*w[0]  + t0.y*w[1]  + t0.z*w[2]  + t0.w*w[3];
    acc += t1.x*w[4]  + t1.y*w[5]  + t1.z*w[6]  + t1.w*w[7];
    acc += t2.x*w[8]  + t2.y*w[9]  + t2.z*w[10] + t2.w*w[11];
    acc += t3.x*w[12] + t3.y*w[13] + t3.z*w[14] + t3.w*w[15];
    return softplus_f(acc);
}

// ---------------- chunked scan pass 1: local cumA + local state ----------------
__global__ void __launch_bounds__(128)
scan_pass1(const __nv_bfloat16* __restrict__ ub, const float* __restrict__ dbc,
           const float* __restrict__ Alog, const float* __restrict__ dtw,
           const float* __restrict__ dtb,
           float* __restrict__ ca, float* __restrict__ cs)
{
    int d = blockIdx.x * 128 + threadIdx.x;
    int c = blockIdx.y;
    int b = blockIdx.z;

    float a2[DS];
    #pragma unroll
    for (int n = 0; n < DS; n++) a2[n] = -__expf(Alog[d*DS + n]) * 1.44269504f;
    bool chain = true;
    #pragma unroll
    for (int n = 1; n < DS; n++)
        if (fabsf(a2[n] - (float)(n+1)*a2[0]) > 1e-4f*fabsf(a2[n])) chain = false;

    float w[DR];
    #pragma unroll
    for (int r = 0; r < DR; r++) w[r] = dtw[r*DI + d];
    float bias = dtb[d];

    const float* bc = dbc + ((size_t)b*SEQL + c*CL)*64;
    const __nv_bfloat16* up = ub + ((size_t)b*SEQL + c*CL)*DI + d;
    size_t o = (((size_t)b*NC + c)*DI + d)*DS;

    if (chain) {
        ull p2[8], s2[8];
        #pragma unroll
        for (int q = 0; q < 8; q++) { p2[q] = pk2(1.f, 1.f); s2[q] = 0ull; }
        float a20 = a2[0];
        for (int l = 0; l < CL; l++) {
            const float4* dtv = (const float4*)(bc + (size_t)l*64);
            float dl  = dt_softplus(dtv, w, bias);
            float duv = dl * __bfloat162float(up[(size_t)l*DI]);
            float e1  = ex2f(dl*a20);
            float e1s = e1*e1;
            ull ep   = pk2(e1, e1s);
            ull es2  = pk2(e1s, e1s);
            ull duv2 = pk2(duv, duv);
            const ulonglong2* B4 = (const ulonglong2*)(bc + (size_t)l*64 + 16);
            #pragma unroll
            for (int j = 0; j < 4; j++) {
                ulonglong2 Bp = B4[j];
                ull db0 = mul2(Bp.x, duv2);
                s2[2*j]   = fma2(ep, s2[2*j],   db0);
                p2[2*j]   = mul2(p2[2*j], ep);
                ep = mul2(ep, es2);
                ull db1 = mul2(Bp.y, duv2);
                s2[2*j+1] = fma2(ep, s2[2*j+1], db1);
                p2[2*j+1] = mul2(p2[2*j+1], ep);
                if (j < 3) ep = mul2(ep, es2);
            }
        }
        #pragma unroll
        for (int q = 0; q < 8; q++) {
            ((ull*)(ca + o))[q] = p2[q];
            ((ull*)(cs + o))[q] = s2[q];
        }
    } else {
        float p[DS], s[DS];
        #pragma unroll
        for (int n = 0; n < DS; n++) { p[n] = 1.f; s[n] = 0.f; }
        for (int l = 0; l < CL; l++) {
            const float4* dtv = (const float4*)(bc + (size_t)l*64);
            float dl  = dt_softplus(dtv, w, bias);
            float duv = dl * __bfloat162float(up[(size_t)l*DI]);
            const float4* Bv = dtv + 4;
            #pragma unroll
            for (int q = 0; q < 4; q++) {
                float4 Bq = Bv[q];
                float e;
                e = ex2f(dl*a2[4*q+0]); p[4*q+0]*=e; s[4*q+0]=e*s[4*q+0]+duv*Bq.x;
                e = ex2f(dl*a2[4*q+1]); p[4*q+1]*=e; s[4*q+1]=e*s[4*q+1]+duv*Bq.y;
                e = ex2f(dl*a2[4*q+2]); p[4*q+2]*=e; s[4*q+2]=e*s[4*q+2]+duv*Bq.z;
                e = ex2f(dl*a2[4*q+3]); p[4*q+3]*=e; s[4*q+3]=e*s[4*q+3]+duv*Bq.w;
            }
        }
        #pragma unroll
        for (int q = 0; q < 4; q++) {
            ((float4*)(ca + o))[q] = make_float4(p[4*q], p[4*q+1], p[4*q+2], p[4*q+3]);
            ((float4*)(cs + o))[q] = make_float4(s[4*q], s[4*q+1], s[4*q+2], s[4*q+3]);
        }
    }
}

// ---------------- pass 2: combine chunk transitions -> h0 per chunk ----------------
__global__ void __launch_bounds__(DI)
scan_pass2(const float* __restrict__ ca, const float* __restrict__ cs,
           float* __restrict__ h0)
{
    int b = blockIdx.x, d = threadIdx.x;
    float h[DS];
    #pragma unroll
    for (int n = 0; n < DS; n++) h[n] = 0.f;
    for (int c = 0; c < NC; c++) {
        size_t o = (((size_t)b*NC + c)*DI + d)*DS;
        #pragma unroll
        for (int q = 0; q < 4; q++)
            ((float4*)(h0 + o))[q] = make_float4(h[4*q], h[4*q+1], h[4*q+2], h[4*q+3]);
        #pragma unroll
        for (int q = 0; q < 4; q++) {
            float4 pq = ((const float4*)(ca + o))[q];
            float4 sq = ((const float4*)(cs + o))[q];
            h[4*q+0] = pq.x*h[4*q+0] + sq.x;
            h[4*q+1] = pq.y*h[4*q+1] + sq.y;
            h[4*q+2] = pq.z*h[4*q+2] + sq.z;
            h[4*q+3] = pq.w*h[4*q+3] + sq.w;
        }
    }
}

// ---------------- pass 3: re-scan from h0, emit y(bf16) = (scan + u*D) * silu(res) ----------------
__global__ void __launch_bounds__(128)
scan_pass3(const __nv_bfloat16* __restrict__ ub, const __nv_bfloat16* __restrict__ resb,
           const float* __restrict__ dbc, const float* __restrict__ Alog,
           const float* __restrict__ dtw, const float* __restrict__ dtb,
           const float* __restrict__ Dp,  const float* __restrict__ h0,
           __nv_bfloat16* __restrict__ y)
{
    int d = blockIdx.x * 128 + threadIdx.x;
    int c = blockIdx.y;
    int b = blockIdx.z;

    float a2[DS];
    #pragma unroll
    for (int n = 0; n < DS; n++) a2[n] = -__expf(Alog[d*DS + n]) * 1.44269504f;
    bool chain = true;
    #pragma unroll
    for (int n = 1; n < DS; n++)
        if (fabsf(a2[n] - (float)(n+1)*a2[0]) > 1e-4f*fabsf(a2[n])) chain = false;

    float w[DR];
    #pragma unroll
    for (int r = 0; r < DR; r++) w[r] = dtw[r*DI + d];
    float bias = dtb[d];
    float Dv = Dp[d];

    const float* bc = dbc + ((size_t)b*SEQL + c*CL)*64;
    const __nv_bfloat16* up = ub   + ((size_t)b*SEQL + c*CL)*DI + d;
    const __nv_bfloat16* rp = resb + ((size_t)b*SEQL + c*CL)*DI + d;
    __nv_bfloat16* yptr = y + ((size_t)b*SEQL + c*CL)*DI + d;
    size_t o0 = (((size_t)b*NC + c)*DI + d)*DS;

    if (chain) {
        ull h2[8];
        #pragma unroll
        for (int q = 0; q < 8; q++) h2[q] = ((const ull*)(h0 + o0))[q];
        float a20 = a2[0];
        for (int l = 0; l < CL; l++) {
            const float4* dtv = (const float4*)(bc + (size_t)l*64);
            float dl  = dt_softplus(dtv, w, bias);
            float uv  = __bfloat162float(up[(size_t)l*DI]);
            float duv = dl * uv;
            float res = __bfloat162float(rp[(size_t)l*DI]);
            float e1  = ex2f(dl*a20);
            float e1s = e1*e1;
            ull ep   = pk2(e1, e1s);
            ull es2  = pk2(e1s, e1s);
            ull duv2 = pk2(duv, duv);
            const ulonglong2* B4 = (const ulonglong2*)(bc + (size_t)l*64 + 16);
            const ulonglong2* C4 = (const ulonglong2*)(bc + (size_t)l*64 + 32);
            ull y2 = 0ull;
            #pragma unroll
            for (int j = 0; j < 4; j++) {
                ulonglong2 Bp = B4[j], Cp = C4[j];
                ull db0 = mul2(Bp.x, duv2);
                h2[2*j] = fma2(ep, h2[2*j], db0);
                y2 = fma2(h2[2*j], Cp.x, y2);
                ep = mul2(ep, es2);
                ull db1 = mul2(Bp.y, duv2);
                h2[2*j+1] = fma2(ep, h2[2*j+1], db1);
                y2 = fma2(h2[2*j+1], Cp.y, y2);
                if (j < 3) ep = mul2(ep, es2);
            }
            float ylo, yhi; upk2(y2, ylo, yhi);
            float ov = ylo + yhi + uv*Dv;
            ov *= res / (1.f + __expf(-res));
            yptr[(size_t)l*DI] = __float2bfloat16(ov);
        }
    } else {
        float h[DS];
        #pragma unroll
        for (int q = 0; q < 4; q++) {
            float4 hq = ((const float4*)(h0 + o0))[q];
            h[4*q] = hq.x; h[4*q+1] = hq.y; h[4*q+2] = hq.z; h[4*q+3] = hq.w;
        }
        for (int l = 0; l < CL; l++) {
            const float4* dtv = (const float4*)(bc + (size_t)l*64);
            float dl  = dt_softplus(dtv, w, bias);
            float uv  = __bfloat162float(up[(size_t)l*DI]);
            float duv = dl * uv;
            float res = __bfloat162float(rp[(size_t)l*DI]);
            const float4* Bv = dtv + 4;
            const float4* Cv = dtv + 8;
            float yv = 0.f;
            #pragma unroll
            for (int q = 0; q < 4; q++) {
                float4 Bq = Bv[q], Cq = Cv[q];
                float e;
                e = ex2f(dl*a2[4*q+0]); h[4*q+0]=e*h[4*q+0]+duv*Bq.x; yv += h[4*q+0]*Cq.x;
                e = ex2f(dl*a2[4*q+1]); h[4*q+1]=e*h[4*q+1]+duv*Bq.y; yv += h[4*q+1]*Cq.y;
                e = ex2f(dl*a2[4*q+2]); h[4*q+2]=e*h[4*q+2]+duv*Bq.z; yv += h[4*q+2]*Cq.z;
                e = ex2f(dl*a2[4*q+3]); h[4*q+3]=e*h[4*q+3]+duv*Bq.w; yv += h[4*q+3]*Cq.w;
            }
            float ov = yv + uv*Dv;
            ov *= res / (1.f + __expf(-res));
            yptr[(size_t)l*DI] = __float2bfloat16(ov);
        }
    }
}

// ---------------- deterministic two-stage mean over L ----------------
__global__ void mean_part_kernel(const float* __restrict__ seq, float* __restrict__ part)
{
    int b = blockIdx.x, c = blockIdx.y, e = threadIdx.x;
    const float* p = seq + ((size_t)b*SEQL + c*64)*DM + e;
    float s = 0.f;
    #pragma unroll 8
    for (int i = 0; i < 64; i++) s += p[(size_t)i*DM];
    part[(b*16 + c)*DM + e] = s;
}
__global__ void mean_final_kernel(const float* __restrict__ part, float* __restrict__ out)
{
    int b = blockIdx.x, e = threadIdx.x;
    float s = 0.f;
    #pragma unroll
    for (int c = 0; c < 16; c++) s += part[(b*16 + c)*DM + e];
    out[b*DM + e] = s * (1.f/1024.f);
}

// ---------------- launch ----------------
extern "C" void kernel_launch(void* const* d_in, const int* in_sizes, int n_in,
                              void* d_out, int out_size)
{
    const float* x    = (const float*)d_in[0];
    const float* plg  = (const float*)d_in[1];
    const float* plb  = (const float*)d_in[2];
    const float* ew   = (const float*)d_in[3];
    const float* eb   = (const float*)d_in[4];
    const float* elg  = (const float*)d_in[5];
    const float* elb  = (const float*)d_in[6];
    const float* rmsw = (const float*)d_in[7];
    const float* inw  = (const float*)d_in[8];
    const float* cw   = (const float*)d_in[9];
    const float* cb   = (const float*)d_in[10];
    const float* xpw  = (const float*)d_in[11];
    const float* dtw  = (const float*)d_in[12];
    const float* dtb  = (const float*)d_in[13];
    const float* Alog = (const float*)d_in[14];
    const float* Dpar = (const float*)d_in[15];
    const float* ow   = (const float*)d_in[16];

    float *seq, *xs, *dbc, *part, *ca, *cs, *h0;
    __nv_bfloat16 *xnb, *resb, *ub, *yb, *inwb, *owb, *xpwb;
    cudaGetSymbolAddress((void**)&seq,   g_seq);
    cudaGetSymbolAddress((void**)&xnb,   g_xnb);
    cudaGetSymbolAddress((void**)&xs,    g_xs);
    cudaGetSymbolAddress((void**)&resb,  g_resb);
    cudaGetSymbolAddress((void**)&ub,    g_ub);
    cudaGetSymbolAddress((void**)&dbc,   g_dbc);
    cudaGetSymbolAddress((void**)&yb,    g_yb);
    cudaGetSymbolAddress((void**)&inwb,  g_inwb);
    cudaGetSymbolAddress((void**)&owb,   g_owb);
    cudaGetSymbolAddress((void**)&xpwb,  g_xpwb);
    cudaGetSymbolAddress((void**)&part,  g_part);
    cudaGetSymbolAddress((void**)&ca,    g_ca);
    cudaGetSymbolAddress((void**)&cs,    g_cs);
    cudaGetSymbolAddress((void**)&h0,    g_h0);

    const int M = BATCH * SEQL;  // 16384

    f2b_kernel<<<(NL*DM*2*DI/4 + 255)/256, 256>>>(inw, inwb, NL*DM*2*DI);
    f2b_kernel<<<(NL*DI*DM/4 + 255)/256, 256>>>(ow, owb, NL*DI*DM);
    pad_xpw_kernel<<<NL*DI*64/256, 256>>>(xpw, xpwb);
    patch_embed_kernel<<<1024, 256>>>(x, plg, plb, ew, eb, elg, elb, seq);

    for (int L = 0; L < NL; L++) {
        rmsnorm_kernel<<<2048, 256>>>(seq, rmsw + L*DM, xnb);

        // in_proj: (16384,256) @ (256,1024) -> xs (fp32) | resb (bf16)
        gemm_bf16<2><<<dim3(16, 128), 256>>>(
            xnb, inwb + (size_t)L*DM*2*DI, xs, resb, M, 2*DI, DM);

        conv_silu_kernel<<<dim3(2,16,16), 256>>>(xs, cw + L*DI*4, cb + L*DI, ub);

        // x_proj: (16384,512) @ (512,64pad) -> dbc (fp32)
        gemm_bf16<0><<<dim3(1, 128), 256>>>(
            ub, xpwb + (size_t)L*DI*64, dbc, nullptr, M, 64, DI);

        scan_pass1<<<dim3(4, NC, BATCH), 128>>>(ub, dbc, Alog + L*DI*DS,
                                                dtw + L*DR*DI, dtb + L*DI, ca, cs);
        scan_pass2<<<BATCH, DI>>>(ca, cs, h0);
        scan_pass3<<<dim3(4, NC, BATCH), 128>>>(ub, resb, dbc, Alog + L*DI*DS,
                                                dtw + L*DR*DI, dtb + L*DI,
                                                Dpar + L*DI, h0, yb);

        // out_proj (+residual into seq): (16384,512) @ (512,256)
        gemm_bf16<1><<<dim3(4, 128), 256>>>(
            yb, owb + (size_t)L*DI*DM, seq, nullptr, M, DM, DI);
    }

    mean_part_kernel<<<dim3(16,16), 256>>>(seq, part);
    mean_final_kernel<<<16, 256>>>(part, (float*)d_out);
}

// round 10
// speedup vs baseline: 1.3589x; 1.1683x over previous
#include <cuda_runtime.h>
#include <cuda_bf16.h>
#include <math.h>

#define BATCH 16
#define SEQL  1024
#define DM    256
#define DI    512
#define DS    16
#define DR    16
#define NL    4
#define NC    16        // scan chunks
#define CL    (SEQL/NC) // 64 steps per chunk

typedef unsigned long long ull;

// ---------------- scratch (static device globals; no allocation) ----------------
__device__ float g_seq  [BATCH*SEQL*DM];
__device__ __nv_bfloat16 g_xnb [BATCH*SEQL*DM];
__device__ float g_xs   [BATCH*SEQL*DI];        // in_proj xs-half (fp32, feeds conv)
__device__ __nv_bfloat16 g_resb[BATCH*SEQL*DI]; // in_proj res-half (bf16)
__device__ __nv_bfloat16 g_ub  [BATCH*SEQL*DI]; // conv+silu output (bf16, sole copy)
__device__ float g_dbc  [BATCH*SEQL*64];
__device__ __nv_bfloat16 g_yb  [BATCH*SEQL*DI];
__device__ __nv_bfloat16 g_inwb[NL*DM*2*DI];
__device__ __nv_bfloat16 g_owb [NL*DI*DM];
__device__ __nv_bfloat16 g_xpwb[NL*DI*64];
__device__ float g_part [BATCH*16*DM];
__device__ float g_ca   [BATCH*NC*DI*DS];
__device__ float g_cs   [BATCH*NC*DI*DS];
__device__ float g_h0   [BATCH*NC*DI*DS];

__device__ __forceinline__ float ex2f(float x) {
    float r; asm("ex2.approx.f32 %0, %1;" : "=f"(r) : "f"(x)); return r;
}
__device__ __forceinline__ float lg2f(float x) {
    float r; asm("lg2.approx.f32 %0, %1;" : "=f"(r) : "f"(x)); return r;
}
__device__ __forceinline__ float softplus_f(float x) {
    float t = ex2f(x * 1.44269504f);
    return (x > 15.f) ? x : 0.69314718f * lg2f(1.f + t);
}
// ---- packed f32x2 helpers (sm_100+) ----
__device__ __forceinline__ ull pk2(float lo, float hi) {
    ull r; asm("mov.b64 %0, {%1,%2};" : "=l"(r) : "f"(lo), "f"(hi)); return r;
}
__device__ __forceinline__ void upk2(ull v, float& lo, float& hi) {
    asm("mov.b64 {%0,%1}, %2;" : "=f"(lo), "=f"(hi) : "l"(v));
}
__device__ __forceinline__ ull mul2(ull a, ull b) {
    ull r; asm("mul.rn.f32x2 %0, %1, %2;" : "=l"(r) : "l"(a), "l"(b)); return r;
}
__device__ __forceinline__ ull fma2(ull a, ull b, ull c) {
    ull r; asm("fma.rn.f32x2 %0, %1, %2, %3;" : "=l"(r) : "l"(a), "l"(b), "l"(c)); return r;
}

// ---------------- fp32 -> bf16 bulk convert ----------------
__global__ void f2b_kernel(const float* __restrict__ src, __nv_bfloat16* __restrict__ dst, int n)
{
    int i = (blockIdx.x * 256 + threadIdx.x) * 4;
    if (i < n) {
        float4 v = *(const float4*)(src + i);
        __nv_bfloat162 p0 = __floats2bfloat162_rn(v.x, v.y);
        __nv_bfloat162 p1 = __floats2bfloat162_rn(v.z, v.w);
        *(uint2*)(dst + i) = make_uint2(*(unsigned*)&p0, *(unsigned*)&p1);
    }
}

// ---------------- pad x_proj_w (L,512,48) -> (L,512,64) bf16 zero-padded ----------------
__global__ void pad_xpw_kernel(const float* __restrict__ xpw, __nv_bfloat16* __restrict__ out)
{
    int idx = blockIdx.x * 256 + threadIdx.x;
    int j  = idx & 63;
    int rk = idx >> 6;
    out[idx] = __float2bfloat16((j < 48) ? xpw[rk*48 + j] : 0.f);
}

// ---------------- patch extract + LN(48) + embed + LN(256); 2 tokens per warp ----------------
__global__ void patch_embed_kernel(const float* __restrict__ x,
                                   const float* __restrict__ plg, const float* __restrict__ plb,
                                   const float* __restrict__ ew,  const float* __restrict__ eb,
                                   const float* __restrict__ elg, const float* __restrict__ elb,
                                   float* __restrict__ seq)
{
    __shared__ float sp[8][2][48];
    int warp = threadIdx.x >> 5, lane = threadIdx.x & 31;
    int tb = blockIdx.x * 16 + warp*2;

    #pragma unroll
    for (int tk = 0; tk < 2; tk++) {
        int t = tb + tk;
        int b = t >> 10, pos = t & 1023;
        int hy = pos >> 5, wx = pos & 31;
        float p1, p2 = 0.f;
        {
            int j = lane;
            int c = j >> 4, py = (j >> 2) & 3, px = j & 3;
            p1 = x[((b*3 + c)*128 + hy*4 + py)*128 + wx*4 + px];
            if (lane < 16) {
                j = 32 + lane;
                c = j >> 4; py = (j >> 2) & 3; px = j & 3;
                p2 = x[((b*3 + c)*128 + hy*4 + py)*128 + wx*4 + px];
            }
        }
        float s = p1 + p2, ss = p1*p1 + p2*p2;
        #pragma unroll
        for (int o = 16; o > 0; o >>= 1) {
            s  += __shfl_xor_sync(0xffffffffu, s,  o);
            ss += __shfl_xor_sync(0xffffffffu, ss, o);
        }
        float mu  = s * (1.f/48.f);
        float var = ss * (1.f/48.f) - mu*mu;
        float rs  = rsqrtf(var + 1e-5f);
        sp[warp][tk][lane] = (p1 - mu)*rs*plg[lane] + plb[lane];
        if (lane < 16) sp[warp][tk][32+lane] = (p2 - mu)*rs*plg[32+lane] + plb[32+lane];
    }
    __syncwarp();

    float acc0[8], acc1[8];
    #pragma unroll
    for (int i = 0; i < 8; i++) { float e = eb[lane + 32*i]; acc0[i] = e; acc1[i] = e; }
    #pragma unroll 4
    for (int j = 0; j < 48; j++) {
        float v0 = sp[warp][0][j], v1 = sp[warp][1][j];
        const float* w = ew + j*DM + lane;
        #pragma unroll
        for (int i = 0; i < 8; i++) {
            float wv = w[32*i];
            acc0[i] += v0 * wv;
            acc1[i] += v1 * wv;
        }
    }
    #pragma unroll
    for (int tk = 0; tk < 2; tk++) {
        float* acc = tk ? acc1 : acc0;
        float s2 = 0.f, ss2 = 0.f;
        #pragma unroll
        for (int i = 0; i < 8; i++) { s2 += acc[i]; ss2 += acc[i]*acc[i]; }
        #pragma unroll
        for (int o = 16; o > 0; o >>= 1) {
            s2  += __shfl_xor_sync(0xffffffffu, s2,  o);
            ss2 += __shfl_xor_sync(0xffffffffu, ss2, o);
        }
        float mu2  = s2 * (1.f/256.f);
        float var2 = ss2 * (1.f/256.f) - mu2*mu2;
        float rs2  = rsqrtf(var2 + 1e-5f);
        int t = tb + tk;
        #pragma unroll
        for (int i = 0; i < 8; i++) {
            int e = lane + 32*i;
            seq[(size_t)t*DM + e] = (acc[i] - mu2)*rs2*elg[e] + elb[e];
        }
    }
}

// ---------------- rmsnorm over DM=256, bf16 output ----------------
__global__ void rmsnorm_kernel(const float* __restrict__ in, const float* __restrict__ w,
                               __nv_bfloat16* __restrict__ out)
{
    int warp = threadIdx.x >> 5, lane = threadIdx.x & 31;
    int t = blockIdx.x * 8 + warp;
    const float4* ip = (const float4*)(in + (size_t)t*DM);
    float4 v0 = ip[lane], v1 = ip[lane+32];
    float ss = v0.x*v0.x+v0.y*v0.y+v0.z*v0.z+v0.w*v0.w
             + v1.x*v1.x+v1.y*v1.y+v1.z*v1.z+v1.w*v1.w;
    #pragma unroll
    for (int o = 16; o > 0; o >>= 1) ss += __shfl_xor_sync(0xffffffffu, ss, o);
    float sc = rsqrtf(ss*(1.f/256.f) + 1e-5f);
    const float4* wp = (const float4*)w;
    float4 w0 = wp[lane], w1 = wp[lane+32];
    __nv_bfloat162 a0 = __floats2bfloat162_rn(v0.x*sc*w0.x, v0.y*sc*w0.y);
    __nv_bfloat162 a1 = __floats2bfloat162_rn(v0.z*sc*w0.z, v0.w*sc*w0.w);
    __nv_bfloat162 b0 = __floats2bfloat162_rn(v1.x*sc*w1.x, v1.y*sc*w1.y);
    __nv_bfloat162 b1 = __floats2bfloat162_rn(v1.z*sc*w1.z, v1.w*sc*w1.w);
    __nv_bfloat16* op = out + (size_t)t*DM;
    *(uint2*)(op + lane*4)      = make_uint2(*(unsigned*)&a0, *(unsigned*)&a1);
    *(uint2*)(op + (lane+32)*4) = make_uint2(*(unsigned*)&b0, *(unsigned*)&b1);
}

// ---------------- BF16 tensor-core GEMM with ldmatrix ----------------
// MODE 0: C fp32. MODE 1: C fp32 += (residual). MODE 2 (in_proj split):
//   cols [0,512)   -> C  fp32 [M,512] (xs half)
//   cols [512,1024)-> Rb bf16 [M,512] (res half)
#define ASTR 40
#define BSTR 72

__device__ __forceinline__ void ldsm4(unsigned* r, unsigned addr) {
    asm volatile("ldmatrix.sync.aligned.m8n8.x4.shared.b16 {%0,%1,%2,%3}, [%4];"
        : "=r"(r[0]), "=r"(r[1]), "=r"(r[2]), "=r"(r[3]) : "r"(addr));
}
__device__ __forceinline__ void ldsm4t(unsigned* r, unsigned addr) {
    asm volatile("ldmatrix.sync.aligned.m8n8.x4.trans.shared.b16 {%0,%1,%2,%3}, [%4];"
        : "=r"(r[0]), "=r"(r[1]), "=r"(r[2]), "=r"(r[3]) : "r"(addr));
}

template<int MODE>
__global__ void __launch_bounds__(256)
gemm_bf16(const __nv_bfloat16* __restrict__ A, const __nv_bfloat16* __restrict__ Bm,
          float* __restrict__ C, __nv_bfloat16* __restrict__ Rb,
          int M, int N, int K)
{
    __shared__ __align__(16) __nv_bfloat16 As[128*ASTR];
    __shared__ __align__(16) __nv_bfloat16 Bs[32*BSTR];
    const int tid  = threadIdx.x;
    const int m0   = blockIdx.y * 128;
    const int n0   = blockIdx.x * 64;
    const int warp = tid >> 5, lane = tid & 31;
    const int g = lane >> 2, t = lane & 3;
    const int wm = (warp & 3) * 32;
    const int wn = (warp >> 2) * 32;

    const int rowa = tid >> 2, ca = tid & 3;
    const int rowb = tid >> 3, cb = tid & 7;
    const __nv_bfloat16* Ap = A + (size_t)(m0 + rowa)*K + ca*8;
    const __nv_bfloat16* Bp = Bm + (size_t)rowb*N + n0 + cb*8;

    unsigned aBase = (unsigned)__cvta_generic_to_shared(As);
    unsigned bBase = (unsigned)__cvta_generic_to_shared(Bs);
    unsigned aAddr[2], bAddr[2];
    {
        int arow = (lane & 15);
        int akh  = (lane >> 4) * 8;
        #pragma unroll
        for (int mt = 0; mt < 2; mt++)
            aAddr[mt] = aBase + (unsigned)((wm + mt*16 + arow)*ASTR + akh)*2u;
        int bkr = ((lane >> 3) & 1)*8 + (lane & 7);
        int bnb = (lane >> 4)*8;
        #pragma unroll
        for (int bp = 0; bp < 2; bp++)
            bAddr[bp] = bBase + (unsigned)(bkr*BSTR + wn + bp*16 + bnb)*2u;
    }

    float acc[2][4][4];
    #pragma unroll
    for (int a = 0; a < 2; a++)
        #pragma unroll
        for (int b = 0; b < 4; b++)
            #pragma unroll
            for (int c = 0; c < 4; c++) acc[a][b][c] = 0.f;

    uint4 ra[2], rb;
    ra[0] = *(const uint4*)Ap;
    ra[1] = *(const uint4*)(Ap + (size_t)64*K);
    rb    = *(const uint4*)Bp;

    for (int k0 = 0; k0 < K; k0 += 32) {
        *(uint4*)&As[rowa*ASTR + ca*8]        = ra[0];
        *(uint4*)&As[(rowa + 64)*ASTR + ca*8] = ra[1];
        *(uint4*)&Bs[rowb*BSTR + cb*8]        = rb;
        __syncthreads();

        if (k0 + 32 < K) {
            ra[0] = *(const uint4*)(Ap + k0 + 32);
            ra[1] = *(const uint4*)(Ap + (size_t)64*K + k0 + 32);
            rb    = *(const uint4*)(Bp + (size_t)(k0 + 32)*N);
        }

        #pragma unroll
        for (int ks = 0; ks < 2; ks++) {
            unsigned af[2][4], bq[2][4];
            ldsm4 (af[0], aAddr[0] + ks*32u);
            ldsm4 (af[1], aAddr[1] + ks*32u);
            ldsm4t(bq[0], bAddr[0] + ks*16u*BSTR*2u);
            ldsm4t(bq[1], bAddr[1] + ks*16u*BSTR*2u);
            #pragma unroll
            for (int mt = 0; mt < 2; mt++)
                #pragma unroll
                for (int nt = 0; nt < 4; nt++) {
                    unsigned b0 = bq[nt>>1][(nt&1)*2];
                    unsigned b1 = bq[nt>>1][(nt&1)*2+1];
                    asm volatile(
                        "mma.sync.aligned.m16n8k16.row.col.f32.bf16.bf16.f32 "
                        "{%0,%1,%2,%3},{%4,%5,%6,%7},{%8,%9},{%0,%1,%2,%3};"
                        : "+f"(acc[mt][nt][0]), "+f"(acc[mt][nt][1]),
                          "+f"(acc[mt][nt][2]), "+f"(acc[mt][nt][3])
                        : "r"(af[mt][0]), "r"(af[mt][1]), "r"(af[mt][2]), "r"(af[mt][3]),
                          "r"(b0), "r"(b1));
                }
        }
        __syncthreads();
    }

    #pragma unroll
    for (int mt = 0; mt < 2; mt++)
        #pragma unroll
        for (int nt = 0; nt < 4; nt++) {
            int row = m0 + wm + mt*16 + g;
            int col = n0 + wn + nt*8 + 2*t;
            if (MODE == 2 && n0 >= 512) {
                int rc = col - 512;   // even -> 4B-aligned bf16x2 store
                __nv_bfloat162 v0 = __floats2bfloat162_rn(acc[mt][nt][0], acc[mt][nt][1]);
                __nv_bfloat162 v1 = __floats2bfloat162_rn(acc[mt][nt][2], acc[mt][nt][3]);
                *(unsigned*)(Rb + (size_t)row*DI + rc)     = *(unsigned*)&v0;
                *(unsigned*)(Rb + (size_t)(row+8)*DI + rc) = *(unsigned*)&v1;
            } else {
                int outN = (MODE == 2) ? DI : N;
                float* p0 = C + (size_t)row*outN + col;
                float* p1 = C + (size_t)(row+8)*outN + col;
                float2 v0 = make_float2(acc[mt][nt][0], acc[mt][nt][1]);
                float2 v1 = make_float2(acc[mt][nt][2], acc[mt][nt][3]);
                if (MODE == 1) {
                    float2 c0 = *(const float2*)p0, c1 = *(const float2*)p1;
                    v0.x += c0.x; v0.y += c0.y; v1.x += c1.x; v1.y += c1.y;
                }
                *(float2*)p0 = v0;
                *(float2*)p1 = v1;
            }
        }
}

// ---------------- depthwise causal conv(4) + SiLU -> ub (bf16 only) ----------------
__global__ void conv_silu_kernel(const float* __restrict__ xs, const float* __restrict__ cw,
                                 const float* __restrict__ cb, __nv_bfloat16* __restrict__ ub)
{
    int d  = blockIdx.x * 256 + threadIdx.x;
    int l0 = blockIdx.y * 64;
    int b  = blockIdx.z;
    float4 w   = *(const float4*)(cw + d*4);
    float bias = cb[d];
    const float* xp = xs + ((size_t)b*SEQL)*DI + d;
    float h0 = (l0 >= 3) ? xp[(size_t)(l0-3)*DI] : 0.f;
    float h1 = (l0 >= 2) ? xp[(size_t)(l0-2)*DI] : 0.f;
    float h2 = (l0 >= 1) ? xp[(size_t)(l0-1)*DI] : 0.f;
    __nv_bfloat16* ubp = ub + ((size_t)b*SEQL + l0)*DI + d;
    #pragma unroll 4
    for (int i = 0; i < 64; i++) {
        float cur = xp[(size_t)(l0+i)*DI];
        float z = bias + w.x*h0 + w.y*h1 + w.z*h2 + w.w*cur;
        float sv = z / (1.f + __expf(-z));
        ubp[(size_t)i*DI] = __float2bfloat16(sv);
        h0 = h1; h1 = h2; h2 = cur;
    }
}

// ---- dt_proj + softplus fused inline (reads from smem-staged dbc) ----
__device__ __forceinline__ float dt_softplus(const float4* dtv, const float* w, float bias)
{
    float4 t0 = dtv[0], t1 = dtv[1], t2 = dtv[2], t3 = dtv[3];
    float acc = bias;
    acc += t0.x*w[0]  + t0.y*w[1]  + t0.z*w[2]  + t0.w*w[3];
    acc += t1.x*w[4]  + t1.y*w[5]  + t1.z*w[6]  + t1.w*w[7];
    acc += t2.x*w[8]  + t2.y*w[9]  + t2.z*w[10] + t2.w*w[11];
    acc += t3.x*w[12] + t3.y*w[13] + t3.z*w[14] + t3.w*w[15];
    return softplus_f(acc);
}

// ---------------- chunked scan pass 1: local cumA + local state ----------------
// dbc staged in smem: 8 float4/step (dt 0..3, B 4..7)
__global__ void __launch_bounds__(128)
scan_pass1(const __nv_bfloat16* __restrict__ ub, const float* __restrict__ dbc,
           const float* __restrict__ Alog, const float* __restrict__ dtw,
           const float* __restrict__ dtb,
           float* __restrict__ ca, float* __restrict__ cs)
{
    __shared__ __align__(16) float4 sdbc[CL*8];
    int tid = threadIdx.x;
    int d = blockIdx.x * 128 + tid;
    int c = blockIdx.y;
    int b = blockIdx.z;

    // cooperative stage: dt + B slices of dbc for this chunk
    {
        const float4* bc4 = (const float4*)(dbc + ((size_t)b*SEQL + c*CL)*64);
        #pragma unroll
        for (int v = tid; v < CL*8; v += 128) {
            int l = v >> 3, j = v & 7;
            sdbc[v] = bc4[l*16 + j];
        }
    }

    float a2[DS];
    #pragma unroll
    for (int n = 0; n < DS; n++) a2[n] = -__expf(Alog[d*DS + n]) * 1.44269504f;
    bool chain = true;
    #pragma unroll
    for (int n = 1; n < DS; n++)
        if (fabsf(a2[n] - (float)(n+1)*a2[0]) > 1e-4f*fabsf(a2[n])) chain = false;

    float w[DR];
    #pragma unroll
    for (int r = 0; r < DR; r++) w[r] = dtw[r*DI + d];
    float bias = dtb[d];

    const __nv_bfloat16* up = ub + ((size_t)b*SEQL + c*CL)*DI + d;
    size_t o = (((size_t)b*NC + c)*DI + d)*DS;
    __syncthreads();

    if (chain) {
        ull p2[8], s2[8];
        #pragma unroll
        for (int q = 0; q < 8; q++) { p2[q] = pk2(1.f, 1.f); s2[q] = 0ull; }
        float a20 = a2[0];
        #pragma unroll 4
        for (int l = 0; l < CL; l++) {
            const float4* dtv = &sdbc[l*8];
            float uv  = __bfloat162float(up[(size_t)l*DI]);
            float dl  = dt_softplus(dtv, w, bias);
            float duv = dl * uv;
            float e1  = ex2f(dl*a20);
            float e1s = e1*e1;
            ull ep   = pk2(e1, e1s);
            ull es2  = pk2(e1s, e1s);
            ull duv2 = pk2(duv, duv);
            const ulonglong2* B4 = (const ulonglong2*)&sdbc[l*8 + 4];
            #pragma unroll
            for (int j = 0; j < 4; j++) {
                ulonglong2 Bp = B4[j];
                ull db0 = mul2(Bp.x, duv2);
                s2[2*j]   = fma2(ep, s2[2*j],   db0);
                p2[2*j]   = mul2(p2[2*j], ep);
                ep = mul2(ep, es2);
                ull db1 = mul2(Bp.y, duv2);
                s2[2*j+1] = fma2(ep, s2[2*j+1], db1);
                p2[2*j+1] = mul2(p2[2*j+1], ep);
                if (j < 3) ep = mul2(ep, es2);
            }
        }
        #pragma unroll
        for (int q = 0; q < 8; q++) {
            ((ull*)(ca + o))[q] = p2[q];
            ((ull*)(cs + o))[q] = s2[q];
        }
    } else {
        float p[DS], s[DS];
        #pragma unroll
        for (int n = 0; n < DS; n++) { p[n] = 1.f; s[n] = 0.f; }
        for (int l = 0; l < CL; l++) {
            const float4* dtv = &sdbc[l*8];
            float dl  = dt_softplus(dtv, w, bias);
            float duv = dl * __bfloat162float(up[(size_t)l*DI]);
            const float4* Bv = &sdbc[l*8 + 4];
            #pragma unroll
            for (int q = 0; q < 4; q++) {
                float4 Bq = Bv[q];
                float e;
                e = ex2f(dl*a2[4*q+0]); p[4*q+0]*=e; s[4*q+0]=e*s[4*q+0]+duv*Bq.x;
                e = ex2f(dl*a2[4*q+1]); p[4*q+1]*=e; s[4*q+1]=e*s[4*q+1]+duv*Bq.y;
                e = ex2f(dl*a2[4*q+2]); p[4*q+2]*=e; s[4*q+2]=e*s[4*q+2]+duv*Bq.z;
                e = ex2f(dl*a2[4*q+3]); p[4*q+3]*=e; s[4*q+3]=e*s[4*q+3]+duv*Bq.w;
            }
        }
        #pragma unroll
        for (int q = 0; q < 4; q++) {
            ((float4*)(ca + o))[q] = make_float4(p[4*q], p[4*q+1], p[4*q+2], p[4*q+3]);
            ((float4*)(cs + o))[q] = make_float4(s[4*q], s[4*q+1], s[4*q+2], s[4*q+3]);
        }
    }
}

// ---------------- pass 2: combine chunk transitions -> h0 per chunk ----------------
__global__ void __launch_bounds__(DI)
scan_pass2(const float* __restrict__ ca, const float* __restrict__ cs,
           float* __restrict__ h0)
{
    int b = blockIdx.x, d = threadIdx.x;
    float h[DS];
    #pragma unroll
    for (int n = 0; n < DS; n++) h[n] = 0.f;
    for (int c = 0; c < NC; c++) {
        size_t o = (((size_t)b*NC + c)*DI + d)*DS;
        #pragma unroll
        for (int q = 0; q < 4; q++)
            ((float4*)(h0 + o))[q] = make_float4(h[4*q], h[4*q+1], h[4*q+2], h[4*q+3]);
        #pragma unroll
        for (int q = 0; q < 4; q++) {
            float4 pq = ((const float4*)(ca + o))[q];
            float4 sq = ((const float4*)(cs + o))[q];
            h[4*q+0] = pq.x*h[4*q+0] + sq.x;
            h[4*q+1] = pq.y*h[4*q+1] + sq.y;
            h[4*q+2] = pq.z*h[4*q+2] + sq.z;
            h[4*q+3] = pq.w*h[4*q+3] + sq.w;
        }
    }
}

// ---------------- pass 3: re-scan from h0, emit y(bf16) = (scan + u*D) * silu(res) ----------------
// dbc staged in smem: 12 float4/step (dt 0..3, B 4..7, C 8..11)
__global__ void __launch_bounds__(128)
scan_pass3(const __nv_bfloat16* __restrict__ ub, const __nv_bfloat16* __restrict__ resb,
           const float* __restrict__ dbc, const float* __restrict__ Alog,
           const float* __restrict__ dtw, const float* __restrict__ dtb,
           const float* __restrict__ Dp,  const float* __restrict__ h0,
           __nv_bfloat16* __restrict__ y)
{
    __shared__ __align__(16) float4 sdbc[CL*12];
    int tid = threadIdx.x;
    int d = blockIdx.x * 128 + tid;
    int c = blockIdx.y;
    int b = blockIdx.z;

    {
        const float4* bc4 = (const float4*)(dbc + ((size_t)b*SEQL + c*CL)*64);
        for (int v = tid; v < CL*12; v += 128) {
            int l = v / 12, j = v - l*12;
            sdbc[v] = bc4[l*16 + j];
        }
    }

    float a2[DS];
    #pragma unroll
    for (int n = 0; n < DS; n++) a2[n] = -__expf(Alog[d*DS + n]) * 1.44269504f;
    bool chain = true;
    #pragma unroll
    for (int n = 1; n < DS; n++)
        if (fabsf(a2[n] - (float)(n+1)*a2[0]) > 1e-4f*fabsf(a2[n])) chain = false;

    float w[DR];
    #pragma unroll
    for (int r = 0; r < DR; r++) w[r] = dtw[r*DI + d];
    float bias = dtb[d];
    float Dv = Dp[d];

    const __nv_bfloat16* up = ub   + ((size_t)b*SEQL + c*CL)*DI + d;
    const __nv_bfloat16* rp = resb + ((size_t)b*SEQL + c*CL)*DI + d;
    __nv_bfloat16* yptr = y + ((size_t)b*SEQL + c*CL)*DI + d;
    size_t o0 = (((size_t)b*NC + c)*DI + d)*DS;
    __syncthreads();

    if (chain) {
        ull h2[8];
        #pragma unroll
        for (int q = 0; q < 8; q++) h2[q] = ((const ull*)(h0 + o0))[q];
        float a20 = a2[0];
        #pragma unroll 4
        for (int l = 0; l < CL; l++) {
            const float4* dtv = &sdbc[l*12];
            float uv  = __bfloat162float(up[(size_t)l*DI]);
            float res = __bfloat162float(rp[(size_t)l*DI]);
            float dl  = dt_softplus(dtv, w, bias);
            float duv = dl * uv;
            float e1  = ex2f(dl*a20);
            float e1s = e1*e1;
            ull ep   = pk2(e1, e1s);
            ull es2  = pk2(e1s, e1s);
            ull duv2 = pk2(duv, duv);
            const ulonglong2* B4 = (const ulonglong2*)&sdbc[l*12 + 4];
            const ulonglong2* C4 = (const ulonglong2*)&sdbc[l*12 + 8];
            ull y2 = 0ull;
            #pragma unroll
            for (int j = 0; j < 4; j++) {
                ulonglong2 Bp = B4[j], Cp = C4[j];
                ull db0 = mul2(Bp.x, duv2);
                h2[2*j] = fma2(ep, h2[2*j], db0);
                y2 = fma2(h2[2*j], Cp.x, y2);
                ep = mul2(ep, es2);
                ull db1 = mul2(Bp.y, duv2);
                h2[2*j+1] = fma2(ep, h2[2*j+1], db1);
                y2 = fma2(h2[2*j+1], Cp.y, y2);
                if (j < 3) ep = mul2(ep, es2);
            }
            float ylo, yhi; upk2(y2, ylo, yhi);
            float ov = ylo + yhi + uv*Dv;
            ov *= res / (1.f + __expf(-res));
            yptr[(size_t)l*DI] = __float2bfloat16(ov);
        }
    } else {
        float h[DS];
        #pragma unroll
        for (int q = 0; q < 4; q++) {
            float4 hq = ((const float4*)(h0 + o0))[q];
            h[4*q] = hq.x; h[4*q+1] = hq.y; h[4*q+2] = hq.z; h[4*q+3] = hq.w;
        }
        for (int l = 0; l < CL; l++) {
            const float4* dtv = &sdbc[l*12];
            float dl  = dt_softplus(dtv, w, bias);
            float uv  = __bfloat162float(up[(size_t)l*DI]);
            float duv = dl * uv;
            float res = __bfloat162float(rp[(size_t)l*DI]);
            const float4* Bv = &sdbc[l*12 + 4];
            const float4* Cv = &sdbc[l*12 + 8];
            float yv = 0.f;
            #pragma unroll
            for (int q = 0; q < 4; q++) {
                float4 Bq = Bv[q], Cq = Cv[q];
                float e;
                e = ex2f(dl*a2[4*q+0]); h[4*q+0]=e*h[4*q+0]+duv*Bq.x; yv += h[4*q+0]*Cq.x;
                e = ex2f(dl*a2[4*q+1]); h[4*q+1]=e*h[4*q+1]+duv*Bq.y; yv += h[4*q+1]*Cq.y;
                e = ex2f(dl*a2[4*q+2]); h[4*q+2]=e*h[4*q+2]+duv*Bq.z; yv += h[4*q+2]*Cq.z;
                e = ex2f(dl*a2[4*q+3]); h[4*q+3]=e*h[4*q+3]+duv*Bq.w; yv += h[4*q+3]*Cq.w;
            }
            float ov = yv + uv*Dv;
            ov *= res / (1.f + __expf(-res));
            yptr[(size_t)l*DI] = __float2bfloat16(ov);
        }
    }
}

// ---------------- deterministic two-stage mean over L ----------------
__global__ void mean_part_kernel(const float* __restrict__ seq, float* __restrict__ part)
{
    int b = blockIdx.x, c = blockIdx.y, e = threadIdx.x;
    const float* p = seq + ((size_t)b*SEQL + c*64)*DM + e;
    float s = 0.f;
    #pragma unroll 8
    for (int i = 0; i < 64; i++) s += p[(size_t)i*DM];
    part[(b*16 + c)*DM + e] = s;
}
__global__ void mean_final_kernel(const float* __restrict__ part, float* __restrict__ out)
{
    int b = blockIdx.x, e = threadIdx.x;
    float s = 0.f;
    #pragma unroll
    for (int c = 0; c < 16; c++) s += part[(b*16 + c)*DM + e];
    out[b*DM + e] = s * (1.f/1024.f);
}

// ---------------- launch ----------------
extern "C" void kernel_launch(void* const* d_in, const int* in_sizes, int n_in,
                              void* d_out, int out_size)
{
    const float* x    = (const float*)d_in[0];
    const float* plg  = (const float*)d_in[1];
    const float* plb  = (const float*)d_in[2];
    const float* ew   = (const float*)d_in[3];
    const float* eb   = (const float*)d_in[4];
    const float* elg  = (const float*)d_in[5];
    const float* elb  = (const float*)d_in[6];
    const float* rmsw = (const float*)d_in[7];
    const float* inw  = (const float*)d_in[8];
    const float* cw   = (const float*)d_in[9];
    const float* cb   = (const float*)d_in[10];
    const float* xpw  = (const float*)d_in[11];
    const float* dtw  = (const float*)d_in[12];
    const float* dtb  = (const float*)d_in[13];
    const float* Alog = (const float*)d_in[14];
    const float* Dpar = (const float*)d_in[15];
    const float* ow   = (const float*)d_in[16];

    float *seq, *xs, *dbc, *part, *ca, *cs, *h0;
    __nv_bfloat16 *xnb, *resb, *ub, *yb, *inwb, *owb, *xpwb;
    cudaGetSymbolAddress((void**)&seq,   g_seq);
    cudaGetSymbolAddress((void**)&xnb,   g_xnb);
    cudaGetSymbolAddress((void**)&xs,    g_xs);
    cudaGetSymbolAddress((void**)&resb,  g_resb);
    cudaGetSymbolAddress((void**)&ub,    g_ub);
    cudaGetSymbolAddress((void**)&dbc,   g_dbc);
    cudaGetSymbolAddress((void**)&yb,    g_yb);
    cudaGetSymbolAddress((void**)&inwb,  g_inwb);
    cudaGetSymbolAddress((void**)&owb,   g_owb);
    cudaGetSymbolAddress((void**)&xpwb,  g_xpwb);
    cudaGetSymbolAddress((void**)&part,  g_part);
    cudaGetSymbolAddress((void**)&ca,    g_ca);
    cudaGetSymbolAddress((void**)&cs,    g_cs);
    cudaGetSymbolAddress((void**)&h0,    g_h0);

    const int M = BATCH * SEQL;  // 16384

    f2b_kernel<<<(NL*DM*2*DI/4 + 255)/256, 256>>>(inw, inwb, NL*DM*2*DI);
    f2b_kernel<<<(NL*DI*DM/4 + 255)/256, 256>>>(ow, owb, NL*DI*DM);
    pad_xpw_kernel<<<NL*DI*64/256, 256>>>(xpw, xpwb);
    patch_embed_kernel<<<1024, 256>>>(x, plg, plb, ew, eb, elg, elb, seq);

    for (int L = 0; L < NL; L++) {
        rmsnorm_kernel<<<2048, 256>>>(seq, rmsw + L*DM, xnb);

        // in_proj: (16384,256) @ (256,1024) -> xs (fp32) | resb (bf16)
        gemm_bf16<2><<<dim3(16, 128), 256>>>(
            xnb, inwb + (size_t)L*DM*2*DI, xs, resb, M, 2*DI, DM);

        conv_silu_kernel<<<dim3(2,16,16), 256>>>(xs, cw + L*DI*4, cb + L*DI, ub);

        // x_proj: (16384,512) @ (512,64pad) -> dbc (fp32)
        gemm_bf16<0><<<dim3(1, 128), 256>>>(
            ub, xpwb + (size_t)L*DI*64, dbc, nullptr, M, 64, DI);

        scan_pass1<<<dim3(4, NC, BATCH), 128>>>(ub, dbc, Alog + L*DI*DS,
                                                dtw + L*DR*DI, dtb + L*DI, ca, cs);
        scan_pass2<<<BATCH, DI>>>(ca, cs, h0);
        scan_pass3<<<dim3(4, NC, BATCH), 128>>>(ub, resb, dbc, Alog + L*DI*DS,
                                                dtw + L*DR*DI, dtb + L*DI,
                                                Dpar + L*DI, h0, yb);

        // out_proj (+residual into seq): (16384,512) @ (512,256)
        gemm_bf16<1><<<dim3(4, 128), 256>>>(
            yb, owb + (size_t)L*DI*DM, seq, nullptr, M, DM, DI);
    }

    mean_part_kernel<<<dim3(16,16), 256>>>(seq, part);
    mean_final_kernel<<<16, 256>>>(part, (float*)d_out);
}

// round 11
// speedup vs baseline: 1.5275x; 1.1241x over previous
#include <cuda_runtime.h>
#include <cuda_bf16.h>
#include <math.h>

#define BATCH 16
#define SEQL  1024
#define DM    256
#define DI    512
#define DS    16
#define DR    16
#define NL    4
#define NC    16        // scan chunks
#define CL    (SEQL/NC) // 64 steps per chunk

typedef unsigned long long ull;

// ---------------- scratch (static device globals; no allocation) ----------------
__device__ float g_seq  [BATCH*SEQL*DM];
__device__ __nv_bfloat16 g_xnb [BATCH*SEQL*DM];
__device__ float g_xs   [BATCH*SEQL*DI];        // in_proj xs-half (fp32, feeds conv)
__device__ __nv_bfloat16 g_resb[BATCH*SEQL*DI]; // in_proj res-half (bf16)
__device__ __nv_bfloat16 g_ub  [BATCH*SEQL*DI]; // conv+silu output (bf16, sole copy)
__device__ float g_dbc  [BATCH*SEQL*64];
__device__ __nv_bfloat16 g_yb  [BATCH*SEQL*DI];
__device__ __nv_bfloat16 g_inwb[NL*DM*2*DI];
__device__ __nv_bfloat16 g_owb [NL*DI*DM];
__device__ __nv_bfloat16 g_xpwb[NL*DI*64];
__device__ float g_part [BATCH*16*DM];
__device__ float g_ca   [BATCH*NC*DI*DS];
__device__ float g_cs   [BATCH*NC*DI*DS];
__device__ float g_h0   [BATCH*NC*DI*DS];

__device__ __forceinline__ float ex2f(float x) {
    float r; asm("ex2.approx.f32 %0, %1;" : "=f"(r) : "f"(x)); return r;
}
__device__ __forceinline__ float lg2f(float x) {
    float r; asm("lg2.approx.f32 %0, %1;" : "=f"(r) : "f"(x)); return r;
}
__device__ __forceinline__ float softplus_f(float x) {
    float t = ex2f(x * 1.44269504f);
    return (x > 15.f) ? x : 0.69314718f * lg2f(1.f + t);
}
// ---- packed f32x2 helpers (sm_100+) ----
__device__ __forceinline__ ull pk2(float lo, float hi) {
    ull r; asm("mov.b64 %0, {%1,%2};" : "=l"(r) : "f"(lo), "f"(hi)); return r;
}
__device__ __forceinline__ void upk2(ull v, float& lo, float& hi) {
    asm("mov.b64 {%0,%1}, %2;" : "=f"(lo), "=f"(hi) : "l"(v));
}
__device__ __forceinline__ ull mul2(ull a, ull b) {
    ull r; asm("mul.rn.f32x2 %0, %1, %2;" : "=l"(r) : "l"(a), "l"(b)); return r;
}
__device__ __forceinline__ ull fma2(ull a, ull b, ull c) {
    ull r; asm("fma.rn.f32x2 %0, %1, %2, %3;" : "=l"(r) : "l"(a), "l"(b), "l"(c)); return r;
}

// ---------------- fp32 -> bf16 bulk convert ----------------
__global__ void f2b_kernel(const float* __restrict__ src, __nv_bfloat16* __restrict__ dst, int n)
{
    int i = (blockIdx.x * 256 + threadIdx.x) * 4;
    if (i < n) {
        float4 v = *(const float4*)(src + i);
        __nv_bfloat162 p0 = __floats2bfloat162_rn(v.x, v.y);
        __nv_bfloat162 p1 = __floats2bfloat162_rn(v.z, v.w);
        *(uint2*)(dst + i) = make_uint2(*(unsigned*)&p0, *(unsigned*)&p1);
    }
}

// ---------------- pad x_proj_w (L,512,48) -> (L,512,64) bf16 zero-padded ----------------
__global__ void pad_xpw_kernel(const float* __restrict__ xpw, __nv_bfloat16* __restrict__ out)
{
    int idx = blockIdx.x * 256 + threadIdx.x;
    int j  = idx & 63;
    int rk = idx >> 6;
    out[idx] = __float2bfloat16((j < 48) ? xpw[rk*48 + j] : 0.f);
}

// ---------------- patch extract + LN(48) + embed + LN(256); 2 tokens per warp ----------------
__global__ void patch_embed_kernel(const float* __restrict__ x,
                                   const float* __restrict__ plg, const float* __restrict__ plb,
                                   const float* __restrict__ ew,  const float* __restrict__ eb,
                                   const float* __restrict__ elg, const float* __restrict__ elb,
                                   float* __restrict__ seq)
{
    __shared__ float sp[8][2][48];
    int warp = threadIdx.x >> 5, lane = threadIdx.x & 31;
    int tb = blockIdx.x * 16 + warp*2;

    #pragma unroll
    for (int tk = 0; tk < 2; tk++) {
        int t = tb + tk;
        int b = t >> 10, pos = t & 1023;
        int hy = pos >> 5, wx = pos & 31;
        float p1, p2 = 0.f;
        {
            int j = lane;
            int c = j >> 4, py = (j >> 2) & 3, px = j & 3;
            p1 = x[((b*3 + c)*128 + hy*4 + py)*128 + wx*4 + px];
            if (lane < 16) {
                j = 32 + lane;
                c = j >> 4; py = (j >> 2) & 3; px = j & 3;
                p2 = x[((b*3 + c)*128 + hy*4 + py)*128 + wx*4 + px];
            }
        }
        float s = p1 + p2, ss = p1*p1 + p2*p2;
        #pragma unroll
        for (int o = 16; o > 0; o >>= 1) {
            s  += __shfl_xor_sync(0xffffffffu, s,  o);
            ss += __shfl_xor_sync(0xffffffffu, ss, o);
        }
        float mu  = s * (1.f/48.f);
        float var = ss * (1.f/48.f) - mu*mu;
        float rs  = rsqrtf(var + 1e-5f);
        sp[warp][tk][lane] = (p1 - mu)*rs*plg[lane] + plb[lane];
        if (lane < 16) sp[warp][tk][32+lane] = (p2 - mu)*rs*plg[32+lane] + plb[32+lane];
    }
    __syncwarp();

    float acc0[8], acc1[8];
    #pragma unroll
    for (int i = 0; i < 8; i++) { float e = eb[lane + 32*i]; acc0[i] = e; acc1[i] = e; }
    #pragma unroll 4
    for (int j = 0; j < 48; j++) {
        float v0 = sp[warp][0][j], v1 = sp[warp][1][j];
        const float* w = ew + j*DM + lane;
        #pragma unroll
        for (int i = 0; i < 8; i++) {
            float wv = w[32*i];
            acc0[i] += v0 * wv;
            acc1[i] += v1 * wv;
        }
    }
    #pragma unroll
    for (int tk = 0; tk < 2; tk++) {
        float* acc = tk ? acc1 : acc0;
        float s2 = 0.f, ss2 = 0.f;
        #pragma unroll
        for (int i = 0; i < 8; i++) { s2 += acc[i]; ss2 += acc[i]*acc[i]; }
        #pragma unroll
        for (int o = 16; o > 0; o >>= 1) {
            s2  += __shfl_xor_sync(0xffffffffu, s2,  o);
            ss2 += __shfl_xor_sync(0xffffffffu, ss2, o);
        }
        float mu2  = s2 * (1.f/256.f);
        float var2 = ss2 * (1.f/256.f) - mu2*mu2;
        float rs2  = rsqrtf(var2 + 1e-5f);
        int t = tb + tk;
        #pragma unroll
        for (int i = 0; i < 8; i++) {
            int e = lane + 32*i;
            seq[(size_t)t*DM + e] = (acc[i] - mu2)*rs2*elg[e] + elb[e];
        }
    }
}

// ---------------- rmsnorm over DM=256, bf16 output ----------------
__global__ void rmsnorm_kernel(const float* __restrict__ in, const float* __restrict__ w,
                               __nv_bfloat16* __restrict__ out)
{
    int warp = threadIdx.x >> 5, lane = threadIdx.x & 31;
    int t = blockIdx.x * 8 + warp;
    const float4* ip = (const float4*)(in + (size_t)t*DM);
    float4 v0 = ip[lane], v1 = ip[lane+32];
    float ss = v0.x*v0.x+v0.y*v0.y+v0.z*v0.z+v0.w*v0.w
             + v1.x*v1.x+v1.y*v1.y+v1.z*v1.z+v1.w*v1.w;
    #pragma unroll
    for (int o = 16; o > 0; o >>= 1) ss += __shfl_xor_sync(0xffffffffu, ss, o);
    float sc = rsqrtf(ss*(1.f/256.f) + 1e-5f);
    const float4* wp = (const float4*)w;
    float4 w0 = wp[lane], w1 = wp[lane+32];
    __nv_bfloat162 a0 = __floats2bfloat162_rn(v0.x*sc*w0.x, v0.y*sc*w0.y);
    __nv_bfloat162 a1 = __floats2bfloat162_rn(v0.z*sc*w0.z, v0.w*sc*w0.w);
    __nv_bfloat162 b0 = __floats2bfloat162_rn(v1.x*sc*w1.x, v1.y*sc*w1.y);
    __nv_bfloat162 b1 = __floats2bfloat162_rn(v1.z*sc*w1.z, v1.w*sc*w1.w);
    __nv_bfloat16* op = out + (size_t)t*DM;
    *(uint2*)(op + lane*4)      = make_uint2(*(unsigned*)&a0, *(unsigned*)&a1);
    *(uint2*)(op + (lane+32)*4) = make_uint2(*(unsigned*)&b0, *(unsigned*)&b1);
}

// ---------------- BF16 tensor-core GEMM with ldmatrix ----------------
// MODE 0: C fp32. MODE 1: C fp32 += (residual). MODE 2 (in_proj split):
//   cols [0,512)   -> C  fp32 [M,512] (xs half)
//   cols [512,1024)-> Rb bf16 [M,512] (res half)
#define ASTR 40
#define BSTR 72

__device__ __forceinline__ void ldsm4(unsigned* r, unsigned addr) {
    asm volatile("ldmatrix.sync.aligned.m8n8.x4.shared.b16 {%0,%1,%2,%3}, [%4];"
        : "=r"(r[0]), "=r"(r[1]), "=r"(r[2]), "=r"(r[3]) : "r"(addr));
}
__device__ __forceinline__ void ldsm4t(unsigned* r, unsigned addr) {
    asm volatile("ldmatrix.sync.aligned.m8n8.x4.trans.shared.b16 {%0,%1,%2,%3}, [%4];"
        : "=r"(r[0]), "=r"(r[1]), "=r"(r[2]), "=r"(r[3]) : "r"(addr));
}

template<int MODE>
__global__ void __launch_bounds__(256)
gemm_bf16(const __nv_bfloat16* __restrict__ A, const __nv_bfloat16* __restrict__ Bm,
          float* __restrict__ C, __nv_bfloat16* __restrict__ Rb,
          int M, int N, int K)
{
    __shared__ __align__(16) __nv_bfloat16 As[128*ASTR];
    __shared__ __align__(16) __nv_bfloat16 Bs[32*BSTR];
    const int tid  = threadIdx.x;
    const int m0   = blockIdx.y * 128;
    const int n0   = blockIdx.x * 64;
    const int warp = tid >> 5, lane = tid & 31;
    const int g = lane >> 2, t = lane & 3;
    const int wm = (warp & 3) * 32;
    const int wn = (warp >> 2) * 32;

    const int rowa = tid >> 2, ca = tid & 3;
    const int rowb = tid >> 3, cb = tid & 7;
    const __nv_bfloat16* Ap = A + (size_t)(m0 + rowa)*K + ca*8;
    const __nv_bfloat16* Bp = Bm + (size_t)rowb*N + n0 + cb*8;

    unsigned aBase = (unsigned)__cvta_generic_to_shared(As);
    unsigned bBase = (unsigned)__cvta_generic_to_shared(Bs);
    unsigned aAddr[2], bAddr[2];
    {
        int arow = (lane & 15);
        int akh  = (lane >> 4) * 8;
        #pragma unroll
        for (int mt = 0; mt < 2; mt++)
            aAddr[mt] = aBase + (unsigned)((wm + mt*16 + arow)*ASTR + akh)*2u;
        int bkr = ((lane >> 3) & 1)*8 + (lane & 7);
        int bnb = (lane >> 4)*8;
        #pragma unroll
        for (int bp = 0; bp < 2; bp++)
            bAddr[bp] = bBase + (unsigned)(bkr*BSTR + wn + bp*16 + bnb)*2u;
    }

    float acc[2][4][4];
    #pragma unroll
    for (int a = 0; a < 2; a++)
        #pragma unroll
        for (int b = 0; b < 4; b++)
            #pragma unroll
            for (int c = 0; c < 4; c++) acc[a][b][c] = 0.f;

    uint4 ra[2], rb;
    ra[0] = *(const uint4*)Ap;
    ra[1] = *(const uint4*)(Ap + (size_t)64*K);
    rb    = *(const uint4*)Bp;

    for (int k0 = 0; k0 < K; k0 += 32) {
        *(uint4*)&As[rowa*ASTR + ca*8]        = ra[0];
        *(uint4*)&As[(rowa + 64)*ASTR + ca*8] = ra[1];
        *(uint4*)&Bs[rowb*BSTR + cb*8]        = rb;
        __syncthreads();

        if (k0 + 32 < K) {
            ra[0] = *(const uint4*)(Ap + k0 + 32);
            ra[1] = *(const uint4*)(Ap + (size_t)64*K + k0 + 32);
            rb    = *(const uint4*)(Bp + (size_t)(k0 + 32)*N);
        }

        #pragma unroll
        for (int ks = 0; ks < 2; ks++) {
            unsigned af[2][4], bq[2][4];
            ldsm4 (af[0], aAddr[0] + ks*32u);
            ldsm4 (af[1], aAddr[1] + ks*32u);
            ldsm4t(bq[0], bAddr[0] + ks*16u*BSTR*2u);
            ldsm4t(bq[1], bAddr[1] + ks*16u*BSTR*2u);
            #pragma unroll
            for (int mt = 0; mt < 2; mt++)
                #pragma unroll
                for (int nt = 0; nt < 4; nt++) {
                    unsigned b0 = bq[nt>>1][(nt&1)*2];
                    unsigned b1 = bq[nt>>1][(nt&1)*2+1];
                    asm volatile(
                        "mma.sync.aligned.m16n8k16.row.col.f32.bf16.bf16.f32 "
                        "{%0,%1,%2,%3},{%4,%5,%6,%7},{%8,%9},{%0,%1,%2,%3};"
                        : "+f"(acc[mt][nt][0]), "+f"(acc[mt][nt][1]),
                          "+f"(acc[mt][nt][2]), "+f"(acc[mt][nt][3])
                        : "r"(af[mt][0]), "r"(af[mt][1]), "r"(af[mt][2]), "r"(af[mt][3]),
                          "r"(b0), "r"(b1));
                }
        }
        __syncthreads();
    }

    #pragma unroll
    for (int mt = 0; mt < 2; mt++)
        #pragma unroll
        for (int nt = 0; nt < 4; nt++) {
            int row = m0 + wm + mt*16 + g;
            int col = n0 + wn + nt*8 + 2*t;
            if (MODE == 2 && n0 >= 512) {
                int rc = col - 512;   // even -> 4B-aligned bf16x2 store
                __nv_bfloat162 v0 = __floats2bfloat162_rn(acc[mt][nt][0], acc[mt][nt][1]);
                __nv_bfloat162 v1 = __floats2bfloat162_rn(acc[mt][nt][2], acc[mt][nt][3]);
                *(unsigned*)(Rb + (size_t)row*DI + rc)     = *(unsigned*)&v0;
                *(unsigned*)(Rb + (size_t)(row+8)*DI + rc) = *(unsigned*)&v1;
            } else {
                int outN = (MODE == 2) ? DI : N;
                float* p0 = C + (size_t)row*outN + col;
                float* p1 = C + (size_t)(row+8)*outN + col;
                float2 v0 = make_float2(acc[mt][nt][0], acc[mt][nt][1]);
                float2 v1 = make_float2(acc[mt][nt][2], acc[mt][nt][3]);
                if (MODE == 1) {
                    float2 c0 = *(const float2*)p0, c1 = *(const float2*)p1;
                    v0.x += c0.x; v0.y += c0.y; v1.x += c1.x; v1.y += c1.y;
                }
                *(float2*)p0 = v0;
                *(float2*)p1 = v1;
            }
        }
}

// ---------------- depthwise causal conv(4) + SiLU -> ub (bf16 only) ----------------
__global__ void conv_silu_kernel(const float* __restrict__ xs, const float* __restrict__ cw,
                                 const float* __restrict__ cb, __nv_bfloat16* __restrict__ ub)
{
    int d  = blockIdx.x * 256 + threadIdx.x;
    int l0 = blockIdx.y * 64;
    int b  = blockIdx.z;
    float4 w   = *(const float4*)(cw + d*4);
    float bias = cb[d];
    const float* xp = xs + ((size_t)b*SEQL)*DI + d;
    float h0 = (l0 >= 3) ? xp[(size_t)(l0-3)*DI] : 0.f;
    float h1 = (l0 >= 2) ? xp[(size_t)(l0-2)*DI] : 0.f;
    float h2 = (l0 >= 1) ? xp[(size_t)(l0-1)*DI] : 0.f;
    __nv_bfloat16* ubp = ub + ((size_t)b*SEQL + l0)*DI + d;
    #pragma unroll 4
    for (int i = 0; i < 64; i++) {
        float cur = xp[(size_t)(l0+i)*DI];
        float z = bias + w.x*h0 + w.y*h1 + w.z*h2 + w.w*cur;
        float sv = z / (1.f + __expf(-z));
        ubp[(size_t)i*DI] = __float2bfloat16(sv);
        h0 = h1; h1 = h2; h2 = cur;
    }
}

// ---- dt_proj + softplus fused inline (reads from smem-staged dbc) ----
__device__ __forceinline__ float dt_softplus(const float4* dtv, const float* w, float bias)
{
    float4 t0 = dtv[0], t1 = dtv[1], t2 = dtv[2], t3 = dtv[3];
    float acc = bias;
    acc += t0.x*w[0]  + t0.y*w[1]  + t0.z*w[2]  + t0.w*w[3];
    acc += t1.x*w[4]  + t1.y*w[5]  + t1.z*w[6]  + t1.w*w[7];
    acc += t2.x*w[8]  + t2.y*w[9]  + t2.z*w[10] + t2.w*w[11];
    acc += t3.x*w[12] + t3.y*w[13] + t3.z*w[14] + t3.w*w[15];
    return softplus_f(acc);
}

// ---------------- chunked scan pass 1: local cumA + local state ----------------
// smem: dbc tile (dt+B, 8 float4/step) + ub tile (CL x 128 bf16)
__global__ void __launch_bounds__(128)
scan_pass1(const __nv_bfloat16* __restrict__ ub, const float* __restrict__ dbc,
           const float* __restrict__ Alog, const float* __restrict__ dtw,
           const float* __restrict__ dtb,
           float* __restrict__ ca, float* __restrict__ cs)
{
    __shared__ __align__(16) float4 sdbc[CL*8];
    __shared__ __align__(16) __nv_bfloat16 su[CL*128];
    int tid = threadIdx.x;
    int d = blockIdx.x * 128 + tid;
    int c = blockIdx.y;
    int b = blockIdx.z;

    // cooperative stage: dt + B slices of dbc
    {
        const float4* bc4 = (const float4*)(dbc + ((size_t)b*SEQL + c*CL)*64);
        #pragma unroll
        for (int v = tid; v < CL*8; v += 128) {
            int l = v >> 3, j = v & 7;
            sdbc[v] = bc4[l*16 + j];
        }
    }
    // cooperative stage: ub tile [CL][128] bf16 (16 uint4 per row)
    {
        const __nv_bfloat16* ug = ub + ((size_t)b*SEQL + c*CL)*DI + blockIdx.x*128;
        uint4* su4 = (uint4*)su;
        #pragma unroll
        for (int v = tid; v < CL*16; v += 128) {
            int l = v >> 4, j = v & 15;
            su4[v] = ((const uint4*)(ug + (size_t)l*DI))[j];
        }
    }

    float a2[DS];
    #pragma unroll
    for (int n = 0; n < DS; n++) a2[n] = -__expf(Alog[d*DS + n]) * 1.44269504f;
    bool chain = true;
    #pragma unroll
    for (int n = 1; n < DS; n++)
        if (fabsf(a2[n] - (float)(n+1)*a2[0]) > 1e-4f*fabsf(a2[n])) chain = false;

    float w[DR];
    #pragma unroll
    for (int r = 0; r < DR; r++) w[r] = dtw[r*DI + d];
    float bias = dtb[d];

    size_t o = (((size_t)b*NC + c)*DI + d)*DS;
    __syncthreads();

    if (chain) {
        ull p2[8], s2[8];
        #pragma unroll
        for (int q = 0; q < 8; q++) { p2[q] = pk2(1.f, 1.f); s2[q] = 0ull; }
        float a20 = a2[0];
        #pragma unroll 4
        for (int l = 0; l < CL; l++) {
            const float4* dtv = &sdbc[l*8];
            float uv  = __bfloat162float(su[l*128 + tid]);
            float dl  = dt_softplus(dtv, w, bias);
            float duv = dl * uv;
            float e1  = ex2f(dl*a20);
            float e1s = e1*e1;
            ull ep   = pk2(e1, e1s);
            ull es2  = pk2(e1s, e1s);
            ull duv2 = pk2(duv, duv);
            const ulonglong2* B4 = (const ulonglong2*)&sdbc[l*8 + 4];
            #pragma unroll
            for (int j = 0; j < 4; j++) {
                ulonglong2 Bp = B4[j];
                ull db0 = mul2(Bp.x, duv2);
                s2[2*j]   = fma2(ep, s2[2*j],   db0);
                p2[2*j]   = mul2(p2[2*j], ep);
                ep = mul2(ep, es2);
                ull db1 = mul2(Bp.y, duv2);
                s2[2*j+1] = fma2(ep, s2[2*j+1], db1);
                p2[2*j+1] = mul2(p2[2*j+1], ep);
                if (j < 3) ep = mul2(ep, es2);
            }
        }
        #pragma unroll
        for (int q = 0; q < 8; q++) {
            ((ull*)(ca + o))[q] = p2[q];
            ((ull*)(cs + o))[q] = s2[q];
        }
    } else {
        float p[DS], s[DS];
        #pragma unroll
        for (int n = 0; n < DS; n++) { p[n] = 1.f; s[n] = 0.f; }
        for (int l = 0; l < CL; l++) {
            const float4* dtv = &sdbc[l*8];
            float dl  = dt_softplus(dtv, w, bias);
            float duv = dl * __bfloat162float(su[l*128 + tid]);
            const float4* Bv = &sdbc[l*8 + 4];
            #pragma unroll
            for (int q = 0; q < 4; q++) {
                float4 Bq = Bv[q];
                float e;
                e = ex2f(dl*a2[4*q+0]); p[4*q+0]*=e; s[4*q+0]=e*s[4*q+0]+duv*Bq.x;
                e = ex2f(dl*a2[4*q+1]); p[4*q+1]*=e; s[4*q+1]=e*s[4*q+1]+duv*Bq.y;
                e = ex2f(dl*a2[4*q+2]); p[4*q+2]*=e; s[4*q+2]=e*s[4*q+2]+duv*Bq.z;
                e = ex2f(dl*a2[4*q+3]); p[4*q+3]*=e; s[4*q+3]=e*s[4*q+3]+duv*Bq.w;
            }
        }
        #pragma unroll
        for (int q = 0; q < 4; q++) {
            ((float4*)(ca + o))[q] = make_float4(p[4*q], p[4*q+1], p[4*q+2], p[4*q+3]);
            ((float4*)(cs + o))[q] = make_float4(s[4*q], s[4*q+1], s[4*q+2], s[4*q+3]);
        }
    }
}

// ---------------- pass 2: combine chunk transitions -> h0 per chunk ----------------
__global__ void __launch_bounds__(DI)
scan_pass2(const float* __restrict__ ca, const float* __restrict__ cs,
           float* __restrict__ h0)
{
    int b = blockIdx.x, d = threadIdx.x;
    float h[DS];
    #pragma unroll
    for (int n = 0; n < DS; n++) h[n] = 0.f;
    for (int c = 0; c < NC; c++) {
        size_t o = (((size_t)b*NC + c)*DI + d)*DS;
        #pragma unroll
        for (int q = 0; q < 4; q++)
            ((float4*)(h0 + o))[q] = make_float4(h[4*q], h[4*q+1], h[4*q+2], h[4*q+3]);
        #pragma unroll
        for (int q = 0; q < 4; q++) {
            float4 pq = ((const float4*)(ca + o))[q];
            float4 sq = ((const float4*)(cs + o))[q];
            h[4*q+0] = pq.x*h[4*q+0] + sq.x;
            h[4*q+1] = pq.y*h[4*q+1] + sq.y;
            h[4*q+2] = pq.z*h[4*q+2] + sq.z;
            h[4*q+3] = pq.w*h[4*q+3] + sq.w;
        }
    }
}

// ---------------- pass 3: re-scan from h0, emit y(bf16) = (scan + u*D) * silu(res) ----------------
// smem: dbc (12 float4/step) + ub tile + res tile
__global__ void __launch_bounds__(128)
scan_pass3(const __nv_bfloat16* __restrict__ ub, const __nv_bfloat16* __restrict__ resb,
           const float* __restrict__ dbc, const float* __restrict__ Alog,
           const float* __restrict__ dtw, const float* __restrict__ dtb,
           const float* __restrict__ Dp,  const float* __restrict__ h0,
           __nv_bfloat16* __restrict__ y)
{
    __shared__ __align__(16) float4 sdbc[CL*12];
    __shared__ __align__(16) __nv_bfloat16 su[CL*128];
    __shared__ __align__(16) __nv_bfloat16 sres[CL*128];
    int tid = threadIdx.x;
    int d = blockIdx.x * 128 + tid;
    int c = blockIdx.y;
    int b = blockIdx.z;

    {
        const float4* bc4 = (const float4*)(dbc + ((size_t)b*SEQL + c*CL)*64);
        for (int v = tid; v < CL*12; v += 128) {
            int l = v / 12, j = v - l*12;
            sdbc[v] = bc4[l*16 + j];
        }
    }
    {
        const __nv_bfloat16* ug = ub   + ((size_t)b*SEQL + c*CL)*DI + blockIdx.x*128;
        const __nv_bfloat16* rg = resb + ((size_t)b*SEQL + c*CL)*DI + blockIdx.x*128;
        uint4* su4 = (uint4*)su;
        uint4* sr4 = (uint4*)sres;
        #pragma unroll
        for (int v = tid; v < CL*16; v += 128) {
            int l = v >> 4, j = v & 15;
            su4[v] = ((const uint4*)(ug + (size_t)l*DI))[j];
            sr4[v] = ((const uint4*)(rg + (size_t)l*DI))[j];
        }
    }

    float a2[DS];
    #pragma unroll
    for (int n = 0; n < DS; n++) a2[n] = -__expf(Alog[d*DS + n]) * 1.44269504f;
    bool chain = true;
    #pragma unroll
    for (int n = 1; n < DS; n++)
        if (fabsf(a2[n] - (float)(n+1)*a2[0]) > 1e-4f*fabsf(a2[n])) chain = false;

    float w[DR];
    #pragma unroll
    for (int r = 0; r < DR; r++) w[r] = dtw[r*DI + d];
    float bias = dtb[d];
    float Dv = Dp[d];

    __nv_bfloat16* yptr = y + ((size_t)b*SEQL + c*CL)*DI + d;
    size_t o0 = (((size_t)b*NC + c)*DI + d)*DS;
    __syncthreads();

    if (chain) {
        ull h2[8];
        #pragma unroll
        for (int q = 0; q < 8; q++) h2[q] = ((const ull*)(h0 + o0))[q];
        float a20 = a2[0];
        #pragma unroll 4
        for (int l = 0; l < CL; l++) {
            const float4* dtv = &sdbc[l*12];
            float uv  = __bfloat162float(su[l*128 + tid]);
            float res = __bfloat162float(sres[l*128 + tid]);
            float dl  = dt_softplus(dtv, w, bias);
            float duv = dl * uv;
            float e1  = ex2f(dl*a20);
            float e1s = e1*e1;
            ull ep   = pk2(e1, e1s);
            ull es2  = pk2(e1s, e1s);
            ull duv2 = pk2(duv, duv);
            const ulonglong2* B4 = (const ulonglong2*)&sdbc[l*12 + 4];
            const ulonglong2* C4 = (const ulonglong2*)&sdbc[l*12 + 8];
            ull y2 = 0ull;
            #pragma unroll
            for (int j = 0; j < 4; j++) {
                ulonglong2 Bp = B4[j], Cp = C4[j];
                ull db0 = mul2(Bp.x, duv2);
                h2[2*j] = fma2(ep, h2[2*j], db0);
                y2 = fma2(h2[2*j], Cp.x, y2);
                ep = mul2(ep, es2);
                ull db1 = mul2(Bp.y, duv2);
                h2[2*j+1] = fma2(ep, h2[2*j+1], db1);
                y2 = fma2(h2[2*j+1], Cp.y, y2);
                if (j < 3) ep = mul2(ep, es2);
            }
            float ylo, yhi; upk2(y2, ylo, yhi);
            float ov = ylo + yhi + uv*Dv;
            ov *= res / (1.f + __expf(-res));
            yptr[(size_t)l*DI] = __float2bfloat16(ov);
        }
    } else {
        float h[DS];
        #pragma unroll
        for (int q = 0; q < 4; q++) {
            float4 hq = ((const float4*)(h0 + o0))[q];
            h[4*q] = hq.x; h[4*q+1] = hq.y; h[4*q+2] = hq.z; h[4*q+3] = hq.w;
        }
        for (int l = 0; l < CL; l++) {
            const float4* dtv = &sdbc[l*12];
            float dl  = dt_softplus(dtv, w, bias);
            float uv  = __bfloat162float(su[l*128 + tid]);
            float duv = dl * uv;
            float res = __bfloat162float(sres[l*128 + tid]);
            const float4* Bv = &sdbc[l*12 + 4];
            const float4* Cv = &sdbc[l*12 + 8];
            float yv = 0.f;
            #pragma unroll
            for (int q = 0; q < 4; q++) {
                float4 Bq = Bv[q], Cq = Cv[q];
                float e;
                e = ex2f(dl*a2[4*q+0]); h[4*q+0]=e*h[4*q+0]+duv*Bq.x; yv += h[4*q+0]*Cq.x;
                e = ex2f(dl*a2[4*q+1]); h[4*q+1]=e*h[4*q+1]+duv*Bq.y; yv += h[4*q+1]*Cq.y;
                e = ex2f(dl*a2[4*q+2]); h[4*q+2]=e*h[4*q+2]+duv*Bq.z; yv += h[4*q+2]*Cq.z;
                e = ex2f(dl*a2[4*q+3]); h[4*q+3]=e*h[4*q+3]+duv*Bq.w; yv += h[4*q+3]*Cq.w;
            }
            float ov = yv + uv*Dv;
            ov *= res / (1.f + __expf(-res));
            yptr[(size_t)l*DI] = __float2bfloat16(ov);
        }
    }
}

// ---------------- deterministic two-stage mean over L ----------------
__global__ void mean_part_kernel(const float* __restrict__ seq, float* __restrict__ part)
{
    int b = blockIdx.x, c = blockIdx.y, e = threadIdx.x;
    const float* p = seq + ((size_t)b*SEQL + c*64)*DM + e;
    float s = 0.f;
    #pragma unroll 8
    for (int i = 0; i < 64; i++) s += p[(size_t)i*DM];
    part[(b*16 + c)*DM + e] = s;
}
__global__ void mean_final_kernel(const float* __restrict__ part, float* __restrict__ out)
{
    int b = blockIdx.x, e = threadIdx.x;
    float s = 0.f;
    #pragma unroll
    for (int c = 0; c < 16; c++) s += part[(b*16 + c)*DM + e];
    out[b*DM + e] = s * (1.f/1024.f);
}

// ---------------- launch ----------------
extern "C" void kernel_launch(void* const* d_in, const int* in_sizes, int n_in,
                              void* d_out, int out_size)
{
    const float* x    = (const float*)d_in[0];
    const float* plg  = (const float*)d_in[1];
    const float* plb  = (const float*)d_in[2];
    const float* ew   = (const float*)d_in[3];
    const float* eb   = (const float*)d_in[4];
    const float* elg  = (const float*)d_in[5];
    const float* elb  = (const float*)d_in[6];
    const float* rmsw = (const float*)d_in[7];
    const float* inw  = (const float*)d_in[8];
    const float* cw   = (const float*)d_in[9];
    const float* cb   = (const float*)d_in[10];
    const float* xpw  = (const float*)d_in[11];
    const float* dtw  = (const float*)d_in[12];
    const float* dtb  = (const float*)d_in[13];
    const float* Alog = (const float*)d_in[14];
    const float* Dpar = (const float*)d_in[15];
    const float* ow   = (const float*)d_in[16];

    float *seq, *xs, *dbc, *part, *ca, *cs, *h0;
    __nv_bfloat16 *xnb, *resb, *ub, *yb, *inwb, *owb, *xpwb;
    cudaGetSymbolAddress((void**)&seq,   g_seq);
    cudaGetSymbolAddress((void**)&xnb,   g_xnb);
    cudaGetSymbolAddress((void**)&xs,    g_xs);
    cudaGetSymbolAddress((void**)&resb,  g_resb);
    cudaGetSymbolAddress((void**)&ub,    g_ub);
    cudaGetSymbolAddress((void**)&dbc,   g_dbc);
    cudaGetSymbolAddress((void**)&yb,    g_yb);
    cudaGetSymbolAddress((void**)&inwb,  g_inwb);
    cudaGetSymbolAddress((void**)&owb,   g_owb);
    cudaGetSymbolAddress((void**)&xpwb,  g_xpwb);
    cudaGetSymbolAddress((void**)&part,  g_part);
    cudaGetSymbolAddress((void**)&ca,    g_ca);
    cudaGetSymbolAddress((void**)&cs,    g_cs);
    cudaGetSymbolAddress((void**)&h0,    g_h0);

    const int M = BATCH * SEQL;  // 16384

    f2b_kernel<<<(NL*DM*2*DI/4 + 255)/256, 256>>>(inw, inwb, NL*DM*2*DI);
    f2b_kernel<<<(NL*DI*DM/4 + 255)/256, 256>>>(ow, owb, NL*DI*DM);
    pad_xpw_kernel<<<NL*DI*64/256, 256>>>(xpw, xpwb);
    patch_embed_kernel<<<1024, 256>>>(x, plg, plb, ew, eb, elg, elb, seq);

    for (int L = 0; L < NL; L++) {
        rmsnorm_kernel<<<2048, 256>>>(seq, rmsw + L*DM, xnb);

        // in_proj: (16384,256) @ (256,1024) -> xs (fp32) | resb (bf16)
        gemm_bf16<2><<<dim3(16, 128), 256>>>(
            xnb, inwb + (size_t)L*DM*2*DI, xs, resb, M, 2*DI, DM);

        conv_silu_kernel<<<dim3(2,16,16), 256>>>(xs, cw + L*DI*4, cb + L*DI, ub);

        // x_proj: (16384,512) @ (512,64pad) -> dbc (fp32)
        gemm_bf16<0><<<dim3(1, 128), 256>>>(
            ub, xpwb + (size_t)L*DI*64, dbc, nullptr, M, 64, DI);

        scan_pass1<<<dim3(4, NC, BATCH), 128>>>(ub, dbc, Alog + L*DI*DS,
                                                dtw + L*DR*DI, dtb + L*DI, ca, cs);
        scan_pass2<<<BATCH, DI>>>(ca, cs, h0);
        scan_pass3<<<dim3(4, NC, BATCH), 128>>>(ub, resb, dbc, Alog + L*DI*DS,
                                                dtw + L*DR*DI, dtb + L*DI,
                                                Dpar + L*DI, h0, yb);

        // out_proj (+residual into seq): (16384,512) @ (512,256)
        gemm_bf16<1><<<dim3(4, 128), 256>>>(
            yb, owb + (size_t)L*DI*DM, seq, nullptr, M, DM, DI);
    }

    mean_part_kernel<<<dim3(16,16), 256>>>(seq, part);
    mean_final_kernel<<<16, 256>>>(part, (float*)d_out);
}

// round 12
// speedup vs baseline: 1.5305x; 1.0019x over previous
#include <cuda_runtime.h>
#include <cuda_bf16.h>
#include <math.h>

#define BATCH 16
#define SEQL  1024
#define DM    256
#define DI    512
#define DS    16
#define DR    16
#define NL    4
#define NC    16        // scan chunks
#define CL    (SEQL/NC) // 64 steps per chunk

typedef unsigned long long ull;

// ---------------- scratch (static device globals; no allocation) ----------------
__device__ float g_seq  [BATCH*SEQL*DM];
__device__ __nv_bfloat16 g_xnb [BATCH*SEQL*DM];
__device__ float g_xs   [BATCH*SEQL*DI];        // in_proj xs-half (fp32, feeds conv)
__device__ __nv_bfloat16 g_resb[BATCH*SEQL*DI]; // in_proj res-half (bf16)
__device__ __nv_bfloat16 g_ub  [BATCH*SEQL*DI]; // conv+silu output (bf16, sole copy)
__device__ float g_dbc  [BATCH*SEQL*64];
__device__ __nv_bfloat16 g_yb  [BATCH*SEQL*DI];
__device__ __nv_bfloat16 g_inwb[NL*DM*2*DI];
__device__ __nv_bfloat16 g_owb [NL*DI*DM];
__device__ __nv_bfloat16 g_xpwb[NL*DI*64];
__device__ float g_part [BATCH*16*DM];
__device__ float g_ca   [BATCH*NC*DI*DS];
__device__ float g_cs   [BATCH*NC*DI*DS];
__device__ float g_h0   [BATCH*NC*DI*DS];

__device__ __forceinline__ float ex2f(float x) {
    float r; asm("ex2.approx.f32 %0, %1;" : "=f"(r) : "f"(x)); return r;
}
__device__ __forceinline__ float lg2f(float x) {
    float r; asm("lg2.approx.f32 %0, %1;" : "=f"(r) : "f"(x)); return r;
}
__device__ __forceinline__ float softplus_f(float x) {
    float t = ex2f(x * 1.44269504f);
    return (x > 15.f) ? x : 0.69314718f * lg2f(1.f + t);
}
// ---- packed f32x2 helpers (sm_100+) ----
__device__ __forceinline__ ull pk2(float lo, float hi) {
    ull r; asm("mov.b64 %0, {%1,%2};" : "=l"(r) : "f"(lo), "f"(hi)); return r;
}
__device__ __forceinline__ void upk2(ull v, float& lo, float& hi) {
    asm("mov.b64 {%0,%1}, %2;" : "=f"(lo), "=f"(hi) : "l"(v));
}
__device__ __forceinline__ ull mul2(ull a, ull b) {
    ull r; asm("mul.rn.f32x2 %0, %1, %2;" : "=l"(r) : "l"(a), "l"(b)); return r;
}
__device__ __forceinline__ ull fma2(ull a, ull b, ull c) {
    ull r; asm("fma.rn.f32x2 %0, %1, %2, %3;" : "=l"(r) : "l"(a), "l"(b), "l"(c)); return r;
}

// ---------------- fp32 -> bf16 bulk convert ----------------
__global__ void f2b_kernel(const float* __restrict__ src, __nv_bfloat16* __restrict__ dst, int n)
{
    int i = (blockIdx.x * 256 + threadIdx.x) * 4;
    if (i < n) {
        float4 v = *(const float4*)(src + i);
        __nv_bfloat162 p0 = __floats2bfloat162_rn(v.x, v.y);
        __nv_bfloat162 p1 = __floats2bfloat162_rn(v.z, v.w);
        *(uint2*)(dst + i) = make_uint2(*(unsigned*)&p0, *(unsigned*)&p1);
    }
}

// ---------------- pad x_proj_w (L,512,48) -> (L,512,64) bf16 zero-padded ----------------
__global__ void pad_xpw_kernel(const float* __restrict__ xpw, __nv_bfloat16* __restrict__ out)
{
    int idx = blockIdx.x * 256 + threadIdx.x;
    int j  = idx & 63;
    int rk = idx >> 6;
    out[idx] = __float2bfloat16((j < 48) ? xpw[rk*48 + j] : 0.f);
}

// ---------------- patch extract + LN(48) + embed + LN(256); 2 tokens per warp ----------------
__global__ void patch_embed_kernel(const float* __restrict__ x,
                                   const float* __restrict__ plg, const float* __restrict__ plb,
                                   const float* __restrict__ ew,  const float* __restrict__ eb,
                                   const float* __restrict__ elg, const float* __restrict__ elb,
                                   float* __restrict__ seq)
{
    __shared__ float sp[8][2][48];
    int warp = threadIdx.x >> 5, lane = threadIdx.x & 31;
    int tb = blockIdx.x * 16 + warp*2;

    #pragma unroll
    for (int tk = 0; tk < 2; tk++) {
        int t = tb + tk;
        int b = t >> 10, pos = t & 1023;
        int hy = pos >> 5, wx = pos & 31;
        float p1, p2 = 0.f;
        {
            int j = lane;
            int c = j >> 4, py = (j >> 2) & 3, px = j & 3;
            p1 = x[((b*3 + c)*128 + hy*4 + py)*128 + wx*4 + px];
            if (lane < 16) {
                j = 32 + lane;
                c = j >> 4; py = (j >> 2) & 3; px = j & 3;
                p2 = x[((b*3 + c)*128 + hy*4 + py)*128 + wx*4 + px];
            }
        }
        float s = p1 + p2, ss = p1*p1 + p2*p2;
        #pragma unroll
        for (int o = 16; o > 0; o >>= 1) {
            s  += __shfl_xor_sync(0xffffffffu, s,  o);
            ss += __shfl_xor_sync(0xffffffffu, ss, o);
        }
        float mu  = s * (1.f/48.f);
        float var = ss * (1.f/48.f) - mu*mu;
        float rs  = rsqrtf(var + 1e-5f);
        sp[warp][tk][lane] = (p1 - mu)*rs*plg[lane] + plb[lane];
        if (lane < 16) sp[warp][tk][32+lane] = (p2 - mu)*rs*plg[32+lane] + plb[32+lane];
    }
    __syncwarp();

    float acc0[8], acc1[8];
    #pragma unroll
    for (int i = 0; i < 8; i++) { float e = eb[lane + 32*i]; acc0[i] = e; acc1[i] = e; }
    #pragma unroll 4
    for (int j = 0; j < 48; j++) {
        float v0 = sp[warp][0][j], v1 = sp[warp][1][j];
        const float* w = ew + j*DM + lane;
        #pragma unroll
        for (int i = 0; i < 8; i++) {
            float wv = w[32*i];
            acc0[i] += v0 * wv;
            acc1[i] += v1 * wv;
        }
    }
    #pragma unroll
    for (int tk = 0; tk < 2; tk++) {
        float* acc = tk ? acc1 : acc0;
        float s2 = 0.f, ss2 = 0.f;
        #pragma unroll
        for (int i = 0; i < 8; i++) { s2 += acc[i]; ss2 += acc[i]*acc[i]; }
        #pragma unroll
        for (int o = 16; o > 0; o >>= 1) {
            s2  += __shfl_xor_sync(0xffffffffu, s2,  o);
            ss2 += __shfl_xor_sync(0xffffffffu, ss2, o);
        }
        float mu2  = s2 * (1.f/256.f);
        float var2 = ss2 * (1.f/256.f) - mu2*mu2;
        float rs2  = rsqrtf(var2 + 1e-5f);
        int t = tb + tk;
        #pragma unroll
        for (int i = 0; i < 8; i++) {
            int e = lane + 32*i;
            seq[(size_t)t*DM + e] = (acc[i] - mu2)*rs2*elg[e] + elb[e];
        }
    }
}

// ---------------- rmsnorm over DM=256, bf16 output ----------------
__global__ void rmsnorm_kernel(const float* __restrict__ in, const float* __restrict__ w,
                               __nv_bfloat16* __restrict__ out)
{
    int warp = threadIdx.x >> 5, lane = threadIdx.x & 31;
    int t = blockIdx.x * 8 + warp;
    const float4* ip = (const float4*)(in + (size_t)t*DM);
    float4 v0 = ip[lane], v1 = ip[lane+32];
    float ss = v0.x*v0.x+v0.y*v0.y+v0.z*v0.z+v0.w*v0.w
             + v1.x*v1.x+v1.y*v1.y+v1.z*v1.z+v1.w*v1.w;
    #pragma unroll
    for (int o = 16; o > 0; o >>= 1) ss += __shfl_xor_sync(0xffffffffu, ss, o);
    float sc = rsqrtf(ss*(1.f/256.f) + 1e-5f);
    const float4* wp = (const float4*)w;
    float4 w0 = wp[lane], w1 = wp[lane+32];
    __nv_bfloat162 a0 = __floats2bfloat162_rn(v0.x*sc*w0.x, v0.y*sc*w0.y);
    __nv_bfloat162 a1 = __floats2bfloat162_rn(v0.z*sc*w0.z, v0.w*sc*w0.w);
    __nv_bfloat162 b0 = __floats2bfloat162_rn(v1.x*sc*w1.x, v1.y*sc*w1.y);
    __nv_bfloat162 b1 = __floats2bfloat162_rn(v1.z*sc*w1.z, v1.w*sc*w1.w);
    __nv_bfloat16* op = out + (size_t)t*DM;
    *(uint2*)(op + lane*4)      = make_uint2(*(unsigned*)&a0, *(unsigned*)&a1);
    *(uint2*)(op + (lane+32)*4) = make_uint2(*(unsigned*)&b0, *(unsigned*)&b1);
}

// ---------------- BF16 tensor-core GEMM with ldmatrix ----------------
// MODE 0: C fp32. MODE 1: C fp32 += (residual). MODE 2 (in_proj split):
//   cols [0,512)   -> C  fp32 [M,512] (xs half)
//   cols [512,1024)-> Rb bf16 [M,512] (res half)
#define ASTR 40
#define BSTR 72

__device__ __forceinline__ void ldsm4(unsigned* r, unsigned addr) {
    asm volatile("ldmatrix.sync.aligned.m8n8.x4.shared.b16 {%0,%1,%2,%3}, [%4];"
        : "=r"(r[0]), "=r"(r[1]), "=r"(r[2]), "=r"(r[3]) : "r"(addr));
}
__device__ __forceinline__ void ldsm4t(unsigned* r, unsigned addr) {
    asm volatile("ldmatrix.sync.aligned.m8n8.x4.trans.shared.b16 {%0,%1,%2,%3}, [%4];"
        : "=r"(r[0]), "=r"(r[1]), "=r"(r[2]), "=r"(r[3]) : "r"(addr));
}

template<int MODE>
__global__ void __launch_bounds__(256)
gemm_bf16(const __nv_bfloat16* __restrict__ A, const __nv_bfloat16* __restrict__ Bm,
          float* __restrict__ C, __nv_bfloat16* __restrict__ Rb,
          int M, int N, int K)
{
    __shared__ __align__(16) __nv_bfloat16 As[128*ASTR];
    __shared__ __align__(16) __nv_bfloat16 Bs[32*BSTR];
    const int tid  = threadIdx.x;
    const int m0   = blockIdx.y * 128;
    const int n0   = blockIdx.x * 64;
    const int warp = tid >> 5, lane = tid & 31;
    const int g = lane >> 2, t = lane & 3;
    const int wm = (warp & 3) * 32;
    const int wn = (warp >> 2) * 32;

    const int rowa = tid >> 2, ca = tid & 3;
    const int rowb = tid >> 3, cb = tid & 7;
    const __nv_bfloat16* Ap = A + (size_t)(m0 + rowa)*K + ca*8;
    const __nv_bfloat16* Bp = Bm + (size_t)rowb*N + n0 + cb*8;

    unsigned aBase = (unsigned)__cvta_generic_to_shared(As);
    unsigned bBase = (unsigned)__cvta_generic_to_shared(Bs);
    unsigned aAddr[2], bAddr[2];
    {
        int arow = (lane & 15);
        int akh  = (lane >> 4) * 8;
        #pragma unroll
        for (int mt = 0; mt < 2; mt++)
            aAddr[mt] = aBase + (unsigned)((wm + mt*16 + arow)*ASTR + akh)*2u;
        int bkr = ((lane >> 3) & 1)*8 + (lane & 7);
        int bnb = (lane >> 4)*8;
        #pragma unroll
        for (int bp = 0; bp < 2; bp++)
            bAddr[bp] = bBase + (unsigned)(bkr*BSTR + wn + bp*16 + bnb)*2u;
    }

    float acc[2][4][4];
    #pragma unroll
    for (int a = 0; a < 2; a++)
        #pragma unroll
        for (int b = 0; b < 4; b++)
            #pragma unroll
            for (int c = 0; c < 4; c++) acc[a][b][c] = 0.f;

    uint4 ra[2], rb;
    ra[0] = *(const uint4*)Ap;
    ra[1] = *(const uint4*)(Ap + (size_t)64*K);
    rb    = *(const uint4*)Bp;

    for (int k0 = 0; k0 < K; k0 += 32) {
        *(uint4*)&As[rowa*ASTR + ca*8]        = ra[0];
        *(uint4*)&As[(rowa + 64)*ASTR + ca*8] = ra[1];
        *(uint4*)&Bs[rowb*BSTR + cb*8]        = rb;
        __syncthreads();

        if (k0 + 32 < K) {
            ra[0] = *(const uint4*)(Ap + k0 + 32);
            ra[1] = *(const uint4*)(Ap + (size_t)64*K + k0 + 32);
            rb    = *(const uint4*)(Bp + (size_t)(k0 + 32)*N);
        }

        #pragma unroll
        for (int ks = 0; ks < 2; ks++) {
            unsigned af[2][4], bq[2][4];
            ldsm4 (af[0], aAddr[0] + ks*32u);
            ldsm4 (af[1], aAddr[1] + ks*32u);
            ldsm4t(bq[0], bAddr[0] + ks*16u*BSTR*2u);
            ldsm4t(bq[1], bAddr[1] + ks*16u*BSTR*2u);
            #pragma unroll
            for (int mt = 0; mt < 2; mt++)
                #pragma unroll
                for (int nt = 0; nt < 4; nt++) {
                    unsigned b0 = bq[nt>>1][(nt&1)*2];
                    unsigned b1 = bq[nt>>1][(nt&1)*2+1];
                    asm volatile(
                        "mma.sync.aligned.m16n8k16.row.col.f32.bf16.bf16.f32 "
                        "{%0,%1,%2,%3},{%4,%5,%6,%7},{%8,%9},{%0,%1,%2,%3};"
                        : "+f"(acc[mt][nt][0]), "+f"(acc[mt][nt][1]),
                          "+f"(acc[mt][nt][2]), "+f"(acc[mt][nt][3])
                        : "r"(af[mt][0]), "r"(af[mt][1]), "r"(af[mt][2]), "r"(af[mt][3]),
                          "r"(b0), "r"(b1));
                }
        }
        __syncthreads();
    }

    #pragma unroll
    for (int mt = 0; mt < 2; mt++)
        #pragma unroll
        for (int nt = 0; nt < 4; nt++) {
            int row = m0 + wm + mt*16 + g;
            int col = n0 + wn + nt*8 + 2*t;
            if (MODE == 2 && n0 >= 512) {
                int rc = col - 512;   // even -> 4B-aligned bf16x2 store
                __nv_bfloat162 v0 = __floats2bfloat162_rn(acc[mt][nt][0], acc[mt][nt][1]);
                __nv_bfloat162 v1 = __floats2bfloat162_rn(acc[mt][nt][2], acc[mt][nt][3]);
                *(unsigned*)(Rb + (size_t)row*DI + rc)     = *(unsigned*)&v0;
                *(unsigned*)(Rb + (size_t)(row+8)*DI + rc) = *(unsigned*)&v1;
            } else {
                int outN = (MODE == 2) ? DI : N;
                float* p0 = C + (size_t)row*outN + col;
                float* p1 = C + (size_t)(row+8)*outN + col;
                float2 v0 = make_float2(acc[mt][nt][0], acc[mt][nt][1]);
                float2 v1 = make_float2(acc[mt][nt][2], acc[mt][nt][3]);
                if (MODE == 1) {
                    float2 c0 = *(const float2*)p0, c1 = *(const float2*)p1;
                    v0.x += c0.x; v0.y += c0.y; v1.x += c1.x; v1.y += c1.y;
                }
                *(float2*)p0 = v0;
                *(float2*)p1 = v1;
            }
        }
}

// ---------------- depthwise causal conv(4) + SiLU -> ub (bf16 only) ----------------
__global__ void conv_silu_kernel(const float* __restrict__ xs, const float* __restrict__ cw,
                                 const float* __restrict__ cb, __nv_bfloat16* __restrict__ ub)
{
    int d  = blockIdx.x * 256 + threadIdx.x;
    int l0 = blockIdx.y * 64;
    int b  = blockIdx.z;
    float4 w   = *(const float4*)(cw + d*4);
    float bias = cb[d];
    const float* xp = xs + ((size_t)b*SEQL)*DI + d;
    float h0 = (l0 >= 3) ? xp[(size_t)(l0-3)*DI] : 0.f;
    float h1 = (l0 >= 2) ? xp[(size_t)(l0-2)*DI] : 0.f;
    float h2 = (l0 >= 1) ? xp[(size_t)(l0-1)*DI] : 0.f;
    __nv_bfloat16* ubp = ub + ((size_t)b*SEQL + l0)*DI + d;
    #pragma unroll 4
    for (int i = 0; i < 64; i++) {
        float cur = xp[(size_t)(l0+i)*DI];
        float z = bias + w.x*h0 + w.y*h1 + w.z*h2 + w.w*cur;
        float sv = z / (1.f + __expf(-z));
        ubp[(size_t)i*DI] = __float2bfloat16(sv);
        h0 = h1; h1 = h2; h2 = cur;
    }
}

// ---- dt_proj + softplus fused inline (reads from smem-staged dbc) ----
__device__ __forceinline__ float dt_softplus(const float4* dtv, const float* w, float bias)
{
    float4 t0 = dtv[0], t1 = dtv[1], t2 = dtv[2], t3 = dtv[3];
    float acc = bias;
    acc += t0.x*w[0]  + t0.y*w[1]  + t0.z*w[2]  + t0.w*w[3];
    acc += t1.x*w[4]  + t1.y*w[5]  + t1.z*w[6]  + t1.w*w[7];
    acc += t2.x*w[8]  + t2.y*w[9]  + t2.z*w[10] + t2.w*w[11];
    acc += t3.x*w[12] + t3.y*w[13] + t3.z*w[14] + t3.w*w[15];
    return softplus_f(acc);
}

// ---------------- chunked scan pass 1: local cumA + local state ----------------
// smem: dbc tile (dt+B, 8 float4/step) + ub tile (CL x 128 bf16)
__global__ void __launch_bounds__(128)
scan_pass1(const __nv_bfloat16* __restrict__ ub, const float* __restrict__ dbc,
           const float* __restrict__ Alog, const float* __restrict__ dtw,
           const float* __restrict__ dtb,
           float* __restrict__ ca, float* __restrict__ cs)
{
    __shared__ __align__(16) float4 sdbc[CL*8];
    __shared__ __align__(16) __nv_bfloat16 su[CL*128];
    int tid = threadIdx.x;
    int d = blockIdx.x * 128 + tid;
    int c = blockIdx.y;
    int b = blockIdx.z;

    // cooperative stage: dt + B slices of dbc
    {
        const float4* bc4 = (const float4*)(dbc + ((size_t)b*SEQL + c*CL)*64);
        #pragma unroll
        for (int v = tid; v < CL*8; v += 128) {
            int l = v >> 3, j = v & 7;
            sdbc[v] = bc4[l*16 + j];
        }
    }
    // cooperative stage: ub tile [CL][128] bf16 (16 uint4 per row)
    {
        const __nv_bfloat16* ug = ub + ((size_t)b*SEQL + c*CL)*DI + blockIdx.x*128;
        uint4* su4 = (uint4*)su;
        #pragma unroll
        for (int v = tid; v < CL*16; v += 128) {
            int l = v >> 4, j = v & 15;
            su4[v] = ((const uint4*)(ug + (size_t)l*DI))[j];
        }
    }

    float a2[DS];
    #pragma unroll
    for (int n = 0; n < DS; n++) a2[n] = -__expf(Alog[d*DS + n]) * 1.44269504f;
    bool chain = true;
    #pragma unroll
    for (int n = 1; n < DS; n++)
        if (fabsf(a2[n] - (float)(n+1)*a2[0]) > 1e-4f*fabsf(a2[n])) chain = false;

    float w[DR];
    #pragma unroll
    for (int r = 0; r < DR; r++) w[r] = dtw[r*DI + d];
    float bias = dtb[d];

    size_t o = (((size_t)b*NC + c)*DI + d)*DS;
    __syncthreads();

    if (chain) {
        ull p2[8], s2[8];
        #pragma unroll
        for (int q = 0; q < 8; q++) { p2[q] = pk2(1.f, 1.f); s2[q] = 0ull; }
        float a20 = a2[0];
        #pragma unroll 4
        for (int l = 0; l < CL; l++) {
            const float4* dtv = &sdbc[l*8];
            float uv  = __bfloat162float(su[l*128 + tid]);
            float dl  = dt_softplus(dtv, w, bias);
            float duv = dl * uv;
            float e1  = ex2f(dl*a20);
            float e1s = e1*e1;
            ull ep   = pk2(e1, e1s);
            ull es2  = pk2(e1s, e1s);
            ull duv2 = pk2(duv, duv);
            const ulonglong2* B4 = (const ulonglong2*)&sdbc[l*8 + 4];
            #pragma unroll
            for (int j = 0; j < 4; j++) {
                ulonglong2 Bp = B4[j];
                ull db0 = mul2(Bp.x, duv2);
                s2[2*j]   = fma2(ep, s2[2*j],   db0);
                p2[2*j]   = mul2(p2[2*j], ep);
                ep = mul2(ep, es2);
                ull db1 = mul2(Bp.y, duv2);
                s2[2*j+1] = fma2(ep, s2[2*j+1], db1);
                p2[2*j+1] = mul2(p2[2*j+1], ep);
                if (j < 3) ep = mul2(ep, es2);
            }
        }
        #pragma unroll
        for (int q = 0; q < 8; q++) {
            ((ull*)(ca + o))[q] = p2[q];
            ((ull*)(cs + o))[q] = s2[q];
        }
    } else {
        float p[DS], s[DS];
        #pragma unroll
        for (int n = 0; n < DS; n++) { p[n] = 1.f; s[n] = 0.f; }
        for (int l = 0; l < CL; l++) {
            const float4* dtv = &sdbc[l*8];
            float dl  = dt_softplus(dtv, w, bias);
            float duv = dl * __bfloat162float(su[l*128 + tid]);
            const float4* Bv = &sdbc[l*8 + 4];
            #pragma unroll
            for (int q = 0; q < 4; q++) {
                float4 Bq = Bv[q];
                float e;
                e = ex2f(dl*a2[4*q+0]); p[4*q+0]*=e; s[4*q+0]=e*s[4*q+0]+duv*Bq.x;
                e = ex2f(dl*a2[4*q+1]); p[4*q+1]*=e; s[4*q+1]=e*s[4*q+1]+duv*Bq.y;
                e = ex2f(dl*a2[4*q+2]); p[4*q+2]*=e; s[4*q+2]=e*s[4*q+2]+duv*Bq.z;
                e = ex2f(dl*a2[4*q+3]); p[4*q+3]*=e; s[4*q+3]=e*s[4*q+3]+duv*Bq.w;
            }
        }
        #pragma unroll
        for (int q = 0; q < 4; q++) {
            ((float4*)(ca + o))[q] = make_float4(p[4*q], p[4*q+1], p[4*q+2], p[4*q+3]);
            ((float4*)(cs + o))[q] = make_float4(s[4*q], s[4*q+1], s[4*q+2], s[4*q+3]);
        }
    }
}

// ---------------- pass 2: combine chunk transitions -> h0 per chunk ----------------
__global__ void __launch_bounds__(DI)
scan_pass2(const float* __restrict__ ca, const float* __restrict__ cs,
           float* __restrict__ h0)
{
    int b = blockIdx.x, d = threadIdx.x;
    float h[DS];
    #pragma unroll
    for (int n = 0; n < DS; n++) h[n] = 0.f;
    for (int c = 0; c < NC; c++) {
        size_t o = (((size_t)b*NC + c)*DI + d)*DS;
        #pragma unroll
        for (int q = 0; q < 4; q++)
            ((float4*)(h0 + o))[q] = make_float4(h[4*q], h[4*q+1], h[4*q+2], h[4*q+3]);
        #pragma unroll
        for (int q = 0; q < 4; q++) {
            float4 pq = ((const float4*)(ca + o))[q];
            float4 sq = ((const float4*)(cs + o))[q];
            h[4*q+0] = pq.x*h[4*q+0] + sq.x;
            h[4*q+1] = pq.y*h[4*q+1] + sq.y;
            h[4*q+2] = pq.z*h[4*q+2] + sq.z;
            h[4*q+3] = pq.w*h[4*q+3] + sq.w;
        }
    }
}

// ---------------- pass 3: re-scan from h0, emit y(bf16) = (scan + u*D) * silu(res) ----------------
// smem: dbc (12 float4/step) + ub tile + res tile
__global__ void __launch_bounds__(128)
scan_pass3(const __nv_bfloat16* __restrict__ ub, const __nv_bfloat16* __restrict__ resb,
           const float* __restrict__ dbc, const float* __restrict__ Alog,
           const float* __restrict__ dtw, const float* __restrict__ dtb,
           const float* __restrict__ Dp,  const float* __restrict__ h0,
           __nv_bfloat16* __restrict__ y)
{
    __shared__ __align__(16) float4 sdbc[CL*12];
    __shared__ __align__(16) __nv_bfloat16 su[CL*128];
    __shared__ __align__(16) __nv_bfloat16 sres[CL*128];
    int tid = threadIdx.x;
    int d = blockIdx.x * 128 + tid;
    int c = blockIdx.y;
    int b = blockIdx.z;

    {
        const float4* bc4 = (const float4*)(dbc + ((size_t)b*SEQL + c*CL)*64);
        for (int v = tid; v < CL*12; v += 128) {
            int l = v / 12, j = v - l*12;
            sdbc[v] = bc4[l*16 + j];
        }
    }
    {
        const __nv_bfloat16* ug = ub   + ((size_t)b*SEQL + c*CL)*DI + blockIdx.x*128;
        const __nv_bfloat16* rg = resb + ((size_t)b*SEQL + c*CL)*DI + blockIdx.x*128;
        uint4* su4 = (uint4*)su;
        uint4* sr4 = (uint4*)sres;
        #pragma unroll
        for (int v = tid; v < CL*16; v += 128) {
            int l = v >> 4, j = v & 15;
            su4[v] = ((const uint4*)(ug + (size_t)l*DI))[j];
            sr4[v] = ((const uint4*)(rg + (size_t)l*DI))[j];
        }
    }

    float a2[DS];
    #pragma unroll
    for (int n = 0; n < DS; n++) a2[n] = -__expf(Alog[d*DS + n]) * 1.44269504f;
    bool chain = true;
    #pragma unroll
    for (int n = 1; n < DS; n++)
        if (fabsf(a2[n] - (float)(n+1)*a2[0]) > 1e-4f*fabsf(a2[n])) chain = false;

    float w[DR];
    #pragma unroll
    for (int r = 0; r < DR; r++) w[r] = dtw[r*DI + d];
    float bias = dtb[d];
    float Dv = Dp[d];

    __nv_bfloat16* yptr = y + ((size_t)b*SEQL + c*CL)*DI + d;
    size_t o0 = (((size_t)b*NC + c)*DI + d)*DS;
    __syncthreads();

    if (chain) {
        ull h2[8];
        #pragma unroll
        for (int q = 0; q < 8; q++) h2[q] = ((const ull*)(h0 + o0))[q];
        float a20 = a2[0];
        #pragma unroll 4
        for (int l = 0; l < CL; l++) {
            const float4* dtv = &sdbc[l*12];
            float uv  = __bfloat162float(su[l*128 + tid]);
            float res = __bfloat162float(sres[l*128 + tid]);
            float dl  = dt_softplus(dtv, w, bias);
            float duv = dl * uv;
            float e1  = ex2f(dl*a20);
            float e1s = e1*e1;
            ull ep   = pk2(e1, e1s);
            ull es2  = pk2(e1s, e1s);
            ull duv2 = pk2(duv, duv);
            const ulonglong2* B4 = (const ulonglong2*)&sdbc[l*12 + 4];
            const ulonglong2* C4 = (const ulonglong2*)&sdbc[l*12 + 8];
            ull y2 = 0ull;
            #pragma unroll
            for (int j = 0; j < 4; j++) {
                ulonglong2 Bp = B4[j], Cp = C4[j];
                ull db0 = mul2(Bp.x, duv2);
                h2[2*j] = fma2(ep, h2[2*j], db0);
                y2 = fma2(h2[2*j], Cp.x, y2);
                ep = mul2(ep, es2);
                ull db1 = mul2(Bp.y, duv2);
                h2[2*j+1] = fma2(ep, h2[2*j+1], db1);
                y2 = fma2(h2[2*j+1], Cp.y, y2);
                if (j < 3) ep = mul2(ep, es2);
            }
            float ylo, yhi; upk2(y2, ylo, yhi);
            float ov = ylo + yhi + uv*Dv;
            ov *= res / (1.f + __expf(-res));
            yptr[(size_t)l*DI] = __float2bfloat16(ov);
        }
    } else {
        float h[DS];
        #pragma unroll
        for (int q = 0; q < 4; q++) {
            float4 hq = ((const float4*)(h0 + o0))[q];
            h[4*q] = hq.x; h[4*q+1] = hq.y; h[4*q+2] = hq.z; h[4*q+3] = hq.w;
        }
        for (int l = 0; l < CL; l++) {
            const float4* dtv = &sdbc[l*12];
            float dl  = dt_softplus(dtv, w, bias);
            float uv  = __bfloat162float(su[l*128 + tid]);
            float duv = dl * uv;
            float res = __bfloat162float(sres[l*128 + tid]);
            const float4* Bv = &sdbc[l*12 + 4];
            const float4* Cv = &sdbc[l*12 + 8];
            float yv = 0.f;
            #pragma unroll
            for (int q = 0; q < 4; q++) {
                float4 Bq = Bv[q], Cq = Cv[q];
                float e;
                e = ex2f(dl*a2[4*q+0]); h[4*q+0]=e*h[4*q+0]+duv*Bq.x; yv += h[4*q+0]*Cq.x;
                e = ex2f(dl*a2[4*q+1]); h[4*q+1]=e*h[4*q+1]+duv*Bq.y; yv += h[4*q+1]*Cq.y;
                e = ex2f(dl*a2[4*q+2]); h[4*q+2]=e*h[4*q+2]+duv*Bq.z; yv += h[4*q+2]*Cq.z;
                e = ex2f(dl*a2[4*q+3]); h[4*q+3]=e*h[4*q+3]+duv*Bq.w; yv += h[4*q+3]*Cq.w;
            }
            float ov = yv + uv*Dv;
            ov *= res / (1.f + __expf(-res));
            yptr[(size_t)l*DI] = __float2bfloat16(ov);
        }
    }
}

// ---------------- deterministic two-stage mean over L ----------------
__global__ void mean_part_kernel(const float* __restrict__ seq, float* __restrict__ part)
{
    int b = blockIdx.x, c = blockIdx.y, e = threadIdx.x;
    const float* p = seq + ((size_t)b*SEQL + c*64)*DM + e;
    float s = 0.f;
    #pragma unroll 8
    for (int i = 0; i < 64; i++) s += p[(size_t)i*DM];
    part[(b*16 + c)*DM + e] = s;
}
__global__ void mean_final_kernel(const float* __restrict__ part, float* __restrict__ out)
{
    int b = blockIdx.x, e = threadIdx.x;
    float s = 0.f;
    #pragma unroll
    for (int c = 0; c < 16; c++) s += part[(b*16 + c)*DM + e];
    out[b*DM + e] = s * (1.f/1024.f);
}

// ---------------- launch ----------------
extern "C" void kernel_launch(void* const* d_in, const int* in_sizes, int n_in,
                              void* d_out, int out_size)
{
    const float* x    = (const float*)d_in[0];
    const float* plg  = (const float*)d_in[1];
    const float* plb  = (const float*)d_in[2];
    const float* ew   = (const float*)d_in[3];
    const float* eb   = (const float*)d_in[4];
    const float* elg  = (const float*)d_in[5];
    const float* elb  = (const float*)d_in[6];
    const float* rmsw = (const float*)d_in[7];
    const float* inw  = (const float*)d_in[8];
    const float* cw   = (const float*)d_in[9];
    const float* cb   = (const float*)d_in[10];
    const float* xpw  = (const float*)d_in[11];
    const float* dtw  = (const float*)d_in[12];
    const float* dtb  = (const float*)d_in[13];
    const float* Alog = (const float*)d_in[14];
    const float* Dpar = (const float*)d_in[15];
    const float* ow   = (const float*)d_in[16];

    float *seq, *xs, *dbc, *part, *ca, *cs, *h0;
    __nv_bfloat16 *xnb, *resb, *ub, *yb, *inwb, *owb, *xpwb;
    cudaGetSymbolAddress((void**)&seq,   g_seq);
    cudaGetSymbolAddress((void**)&xnb,   g_xnb);
    cudaGetSymbolAddress((void**)&xs,    g_xs);
    cudaGetSymbolAddress((void**)&resb,  g_resb);
    cudaGetSymbolAddress((void**)&ub,    g_ub);
    cudaGetSymbolAddress((void**)&dbc,   g_dbc);
    cudaGetSymbolAddress((void**)&yb,    g_yb);
    cudaGetSymbolAddress((void**)&inwb,  g_inwb);
    cudaGetSymbolAddress((void**)&owb,   g_owb);
    cudaGetSymbolAddress((void**)&xpwb,  g_xpwb);
    cudaGetSymbolAddress((void**)&part,  g_part);
    cudaGetSymbolAddress((void**)&ca,    g_ca);
    cudaGetSymbolAddress((void**)&cs,    g_cs);
    cudaGetSymbolAddress((void**)&h0,    g_h0);

    const int M = BATCH * SEQL;  // 16384

    f2b_kernel<<<(NL*DM*2*DI/4 + 255)/256, 256>>>(inw, inwb, NL*DM*2*DI);
    f2b_kernel<<<(NL*DI*DM/4 + 255)/256, 256>>>(ow, owb, NL*DI*DM);
    pad_xpw_kernel<<<NL*DI*64/256, 256>>>(xpw, xpwb);
    patch_embed_kernel<<<1024, 256>>>(x, plg, plb, ew, eb, elg, elb, seq);

    for (int L = 0; L < NL; L++) {
        rmsnorm_kernel<<<2048, 256>>>(seq, rmsw + L*DM, xnb);

        // in_proj: (16384,256) @ (256,1024) -> xs (fp32) | resb (bf16)
        gemm_bf16<2><<<dim3(16, 128), 256>>>(
            xnb, inwb + (size_t)L*DM*2*DI, xs, resb, M, 2*DI, DM);

        conv_silu_kernel<<<dim3(2,16,16), 256>>>(xs, cw + L*DI*4, cb + L*DI, ub);

        // x_proj: (16384,512) @ (512,64pad) -> dbc (fp32)
        gemm_bf16<0><<<dim3(1, 128), 256>>>(
            ub, xpwb + (size_t)L*DI*64, dbc, nullptr, M, 64, DI);

        scan_pass1<<<dim3(4, NC, BATCH), 128>>>(ub, dbc, Alog + L*DI*DS,
                                                dtw + L*DR*DI, dtb + L*DI, ca, cs);
        scan_pass2<<<BATCH, DI>>>(ca, cs, h0);
        scan_pass3<<<dim3(4, NC, BATCH), 128>>>(ub, resb, dbc, Alog + L*DI*DS,
                                                dtw + L*DR*DI, dtb + L*DI,
                                                Dpar + L*DI, h0, yb);

        // out_proj (+residual into seq): (16384,512) @ (512,256)
        gemm_bf16<1><<<dim3(4, 128), 256>>>(
            yb, owb + (size_t)L*DI*DM, seq, nullptr, M, DM, DI);
    }

    mean_part_kernel<<<dim3(16,16), 256>>>(seq, part);
    mean_final_kernel<<<16, 256>>>(part, (float*)d_out);
}